// round 7
// baseline (speedup 1.0000x reference)
#include <cuda_runtime.h>
#include <cstdint>

// Problem constants (match reference)
#define NN   30000
#define EE   300000
#define NG   512
#define HID  600
#define INF  9
#define NT   128
#define CHID 256

// ---------------- device scratch (allocation-free rule: device globals) ----
__device__ float g_h[NN * HID];
__device__ float g_agg[NN * HID];
__device__ float g_t1[NN * HID];
__device__ float g_feats[NG * HID];
__device__ float g_z1[NG * CHID];
__device__ float g_z2[NG * CHID];

__device__ int g_src[EE];
__device__ int g_dst[EE];
__device__ int g_batch[NN];
__device__ int g_deg[NN];
__device__ int g_rowptr[NN + 1];
__device__ int g_cursor[NN];
__device__ int g_col[EE];
__device__ int g_is64;

// ---------------- index dtype detection + conversion ----------------------
__global__ void k_detect(const unsigned long long* __restrict__ p) {
    if (threadIdx.x == 0 && blockIdx.x == 0) {
        int is64 = 1;
        for (int i = 0; i < 256; i++)
            if (p[i] >> 32) { is64 = 0; break; }
        g_is64 = is64;
    }
}

__global__ void k_convert(const void* __restrict__ edges,
                          const void* __restrict__ batch) {
    int i = blockIdx.x * blockDim.x + threadIdx.x;
    int is64 = g_is64;
    if (i < EE) {
        if (is64) {
            const long long* p = (const long long*)edges;
            g_src[i] = (int)p[i];
            g_dst[i] = (int)p[EE + i];
        } else {
            const int* p = (const int*)edges;
            g_src[i] = p[i];
            g_dst[i] = p[EE + i];
        }
    }
    if (i < NN) {
        if (is64) {
            const long long* p = (const long long*)batch;
            g_batch[i] = (int)p[i];
        } else {
            const int* p = (const int*)batch;
            g_batch[i] = p[i];
        }
    }
}

// ---------------- small utility kernels ------------------------------------
__global__ void k_zero_int(int* p, int n) {
    int i = blockIdx.x * blockDim.x + threadIdx.x;
    if (i < n) p[i] = 0;
}
__global__ void k_zero_float(float* p, int n) {
    int i = blockIdx.x * blockDim.x + threadIdx.x;
    if (i < n) p[i] = 0.f;
}
__global__ void k_copy_int(const int* __restrict__ a, int* __restrict__ b, int n) {
    int i = blockIdx.x * blockDim.x + threadIdx.x;
    if (i < n) b[i] = a[i];
}

// ---------------- CSR build (dst-major) ------------------------------------
__global__ void k_count(const int* __restrict__ dst, int* __restrict__ deg) {
    int i = blockIdx.x * blockDim.x + threadIdx.x;
    if (i < EE) atomicAdd(&deg[dst[i]], 1);
}

__global__ void k_scan(const int* __restrict__ in, int* __restrict__ out, int n) {
    __shared__ int s[1024];
    __shared__ int s_carry;
    int tid = threadIdx.x;
    if (tid == 0) s_carry = 0;
    __syncthreads();
    for (int base = 0; base < n; base += 1024) {
        int i = base + tid;
        int v = (i < n) ? in[i] : 0;
        s[tid] = v;
        __syncthreads();
        for (int off = 1; off < 1024; off <<= 1) {
            int t = (tid >= off) ? s[tid - off] : 0;
            __syncthreads();
            s[tid] += t;
            __syncthreads();
        }
        int c = s_carry;
        if (i < n) out[i] = c + s[tid] - v;
        __syncthreads();
        if (tid == 0) s_carry = c + s[1023];
        __syncthreads();
    }
    if (tid == 0) out[n] = s_carry;
}

__global__ void k_fill(const int* __restrict__ src, const int* __restrict__ dst,
                       int* __restrict__ cursor, int* __restrict__ col) {
    int i = blockIdx.x * blockDim.x + threadIdx.x;
    if (i < EE) {
        int p = atomicAdd(&cursor[dst[i]], 1);
        col[p] = src[i];
    }
}

// ---------------- aggregation --------------------------------------------
__global__ void k_aggregate(const float* __restrict__ h, float* __restrict__ agg,
                            const int* __restrict__ rowptr,
                            const int* __restrict__ col, int width) {
    __shared__ int s_nbr[64];
    int node = blockIdx.x;
    int f = threadIdx.x;
    int CH = (blockDim.x < 64) ? blockDim.x : 64;
    int start = rowptr[node], end = rowptr[node + 1];
    float acc = (f < width) ? h[node * width + f] : 0.f;
    for (int base = start; base < end; base += CH) {
        int cnt = end - base;
        if (cnt > CH) cnt = CH;
        if ((int)threadIdx.x < cnt) s_nbr[threadIdx.x] = col[base + threadIdx.x];
        __syncthreads();
        if (f < width) {
            for (int j = 0; j < cnt; j++)
                acc += h[s_nbr[j] * width + f];
        }
        __syncthreads();
    }
    if (f < width) agg[node * width + f] = acc;
}

__global__ void k_aggregate_v4(const float* __restrict__ h, float* __restrict__ agg,
                               const int* __restrict__ rowptr,
                               const int* __restrict__ col) {
    __shared__ int s_nbr[32];
    int node = blockIdx.x;
    int f4 = threadIdx.x;                  // 0..159, use first 150
    int start = rowptr[node], end = rowptr[node + 1];
    const float4* hv = (const float4*)h;
    float4 acc;
    if (f4 < 150) acc = hv[node * 150 + f4];
    else acc = make_float4(0.f, 0.f, 0.f, 0.f);
    for (int base = start; base < end; base += 32) {
        int cnt = end - base;
        if (cnt > 32) cnt = 32;
        if ((int)threadIdx.x < cnt) s_nbr[threadIdx.x] = col[base + threadIdx.x];
        __syncthreads();
        if (f4 < 150) {
            for (int j = 0; j < cnt; j++) {
                float4 v = hv[s_nbr[j] * 150 + f4];
                acc.x += v.x; acc.y += v.y; acc.z += v.z; acc.w += v.w;
            }
        }
        __syncthreads();
    }
    if (f4 < 150) ((float4*)agg)[node * 150 + f4] = acc;
}

// ---------------- pooling --------------------------------------------------
__global__ void k_pool(const float* __restrict__ h, const int* __restrict__ batch,
                       float* __restrict__ feats) {
    int idx = blockIdx.x * blockDim.x + threadIdx.x;
    if (idx >= NN * HID) return;
    int n = idx / HID;
    int f = idx - n * HID;
    atomicAdd(&feats[batch[n] * HID + f], h[idx]);
}

// ---------------- FFMA SGEMM (small GEMMs: K=9 layer0, classifier) ---------
#define BM 128
#define BN 128
#define BK 8

__global__ __launch_bounds__(256)
void k_sgemm(int M, int N, int K,
             const float* __restrict__ A, const float* __restrict__ B,
             const float* __restrict__ bias, float* __restrict__ C, int relu) {
    __shared__ float As[BK][BM + 4];
    __shared__ float Bs[BK][BN];

    int tid = threadIdx.x;
    int tx = tid & 15;
    int ty = tid >> 4;
    int m0 = blockIdx.y * BM;
    int n0 = blockIdx.x * BN;

    float acc[8][8];
#pragma unroll
    for (int i = 0; i < 8; i++)
#pragma unroll
        for (int j = 0; j < 8; j++) acc[i][j] = 0.f;

    for (int k0 = 0; k0 < K; k0 += BK) {
#pragma unroll
        for (int i = 0; i < 4; i++) {
            int e = tid * 4 + i;
            int m = e >> 3, k = e & 7;
            int gm = m0 + m, gk = k0 + k;
            As[k][m] = (gm < M && gk < K) ? A[gm * K + gk] : 0.f;
        }
#pragma unroll
        for (int i = 0; i < 4; i++) {
            int e = tid * 4 + i;
            int k = e >> 7, n = e & 127;
            int gn = n0 + n, gk = k0 + k;
            Bs[k][n] = (gn < N && gk < K) ? B[gk * N + gn] : 0.f;
        }
        __syncthreads();

#pragma unroll
        for (int k = 0; k < BK; k++) {
            float4 a0 = *(const float4*)&As[k][ty * 4];
            float4 a1 = *(const float4*)&As[k][64 + ty * 4];
            float4 b0 = *(const float4*)&Bs[k][tx * 4];
            float4 b1 = *(const float4*)&Bs[k][64 + tx * 4];
            float a[8] = {a0.x, a0.y, a0.z, a0.w, a1.x, a1.y, a1.z, a1.w};
            float b[8] = {b0.x, b0.y, b0.z, b0.w, b1.x, b1.y, b1.z, b1.w};
#pragma unroll
            for (int i = 0; i < 8; i++)
#pragma unroll
                for (int j = 0; j < 8; j++)
                    acc[i][j] = fmaf(a[i], b[j], acc[i][j]);
        }
        __syncthreads();
    }

#pragma unroll
    for (int i = 0; i < 8; i++) {
        int r = (i < 4) ? (ty * 4 + i) : (64 + ty * 4 + (i - 4));
        int gm = m0 + r;
        if (gm >= M) continue;
#pragma unroll
        for (int j = 0; j < 8; j++) {
            int c = (j < 4) ? (tx * 4 + j) : (64 + tx * 4 + (j - 4));
            int gn = n0 + c;
            if (gn >= N) continue;
            float v = acc[i][j] + bias[gn];
            if (relu) v = fmaxf(v, 0.f);
            C[gm * N + gn] = v;
        }
    }
}

// ---------------- 3xTF32 mma.sync GEMM, fragment-order smem ----------------
// C = act(A[M,K] @ B[K,N] + bias). 128x128x16 block tile, 256 threads
// (8 warps as 4x2, warp tile 32x64). Operands stored in smem in m16n8k8
// fragment order so fragment loads are LDS.128 (A) / LDS.64 (B).
// tf32 hi/lo split, 3 mma passes per fragment (hi*hi + hi*lo + lo*hi).
#define GBM 128
#define GBN 128
#define GBK 16
// per-buffer float offsets in fragment layout
#define OFF_AH 0
#define OFF_AL 2048
#define OFF_BH 4096
#define OFF_BL 6144
#define BUF_FLOATS 8192                  // 32 KB
#define GSM_TOTAL_BYTES (2 * BUF_FLOATS * 4)   // 64 KB

__device__ __forceinline__ unsigned f2tf32(float x) {
    unsigned r;
    asm("cvt.rna.tf32.f32 %0, %1;" : "=r"(r) : "f"(x));
    return r;
}

__device__ __forceinline__ void mma_tf32(float* d, const float4 a,
                                         float b0, float b1) {
    asm volatile(
        "mma.sync.aligned.m16n8k8.row.col.f32.tf32.tf32.f32 "
        "{%0,%1,%2,%3}, {%4,%5,%6,%7}, {%8,%9}, {%0,%1,%2,%3};\n"
        : "+f"(d[0]), "+f"(d[1]), "+f"(d[2]), "+f"(d[3])
        : "r"(__float_as_uint(a.x)), "r"(__float_as_uint(a.y)),
          "r"(__float_as_uint(a.z)), "r"(__float_as_uint(a.w)),
          "r"(__float_as_uint(b0)), "r"(__float_as_uint(b1)));
}

// A fragment slot for tile element (m in [0,128), k in [0,16))
__device__ __forceinline__ int a_frag_idx(int m, int k) {
    int s = k >> 3, kk = k & 7;
    int mtile = m >> 4, mrow = m & 15;
    int lane = (mrow & 7) * 4 + (kk & 3);
    int reg = ((mrow >> 3) & 1) | ((kk >> 2) << 1);
    return ((s * 8 + mtile) * 32 + lane) * 4 + reg;
}
// B fragment slot for tile element (k in [0,16), n in [0,128))
__device__ __forceinline__ int b_frag_idx(int k, int n) {
    int s = k >> 3, kk = k & 7;
    int ntile = n >> 3, ncol = n & 7;
    int lane = ncol * 4 + (kk & 3);
    int reg = (kk >> 2) & 1;
    return ((s * 16 + ntile) * 32 + lane) * 2 + reg;
}

__global__ __launch_bounds__(256, 1)
void k_gemm_tf32(int M, int N, int K,
                 const float* __restrict__ A, const float* __restrict__ B,
                 const float* __restrict__ bias, float* __restrict__ C, int relu) {
    extern __shared__ float sm[];

    int tid = threadIdx.x;
    int lane = tid & 31;
    int warp = tid >> 5;
    int wm = (warp >> 1) * 32;   // warp row offset in tile
    int wn = (warp & 1) * 64;    // warp col offset in tile
    int lq = lane >> 2;          // 0..7
    int lr = lane & 3;           // 0..3

    int m0 = blockIdx.y * GBM;
    int n0 = blockIdx.x * GBN;
    bool m_full = (m0 + GBM <= M);
    bool n_full = (n0 + GBN <= N);

    // global load mappings
    int a_m = tid >> 1;               // 0..127
    int a_k = (tid & 1) * 8;          // 0 or 8
    int b_k = tid >> 4;               // 0..15
    int b_n = (tid & 15) * 8;         // 0..120

    // precomputed frag indices for this thread's 8 A / 8 B elements
    int ai[8], bi[8];
#pragma unroll
    for (int i = 0; i < 8; i++) {
        ai[i] = a_frag_idx(a_m, a_k + i);
        bi[i] = b_frag_idx(b_k, b_n + i);
    }

    float acc[2][8][4];
#pragma unroll
    for (int i = 0; i < 2; i++)
#pragma unroll
        for (int j = 0; j < 8; j++)
#pragma unroll
            for (int c = 0; c < 4; c++) acc[i][j][c] = 0.f;

    float ra[8], rb[8];
    int NIT = (K + GBK - 1) / GBK;

    // ---- prologue: load + convert + STS tile 0 ----
    {
        bool k_full = (GBK <= K);
        if (m_full && k_full) {
            const float* p = &A[(m0 + a_m) * K + a_k];
            float4 v0 = *(const float4*)p;
            float4 v1 = *(const float4*)(p + 4);
            ra[0] = v0.x; ra[1] = v0.y; ra[2] = v0.z; ra[3] = v0.w;
            ra[4] = v1.x; ra[5] = v1.y; ra[6] = v1.z; ra[7] = v1.w;
        } else {
#pragma unroll
            for (int i = 0; i < 8; i++) {
                int gm = m0 + a_m, gk = a_k + i;
                ra[i] = (gm < M && gk < K) ? A[gm * K + gk] : 0.f;
            }
        }
        if (n_full && k_full) {
            const float* p = &B[b_k * N + n0 + b_n];
            float4 v0 = *(const float4*)p;
            float4 v1 = *(const float4*)(p + 4);
            rb[0] = v0.x; rb[1] = v0.y; rb[2] = v0.z; rb[3] = v0.w;
            rb[4] = v1.x; rb[5] = v1.y; rb[6] = v1.z; rb[7] = v1.w;
        } else {
#pragma unroll
            for (int i = 0; i < 8; i++) {
                int gk = b_k, gn = n0 + b_n + i;
                rb[i] = (gk < K && gn < N) ? B[gk * N + gn] : 0.f;
            }
        }
#pragma unroll
        for (int i = 0; i < 8; i++) {
            unsigned hi = f2tf32(ra[i]);
            float lo = ra[i] - __uint_as_float(hi);
            sm[OFF_AH + ai[i]] = __uint_as_float(hi);
            sm[OFF_AL + ai[i]] = __uint_as_float(f2tf32(lo));
        }
#pragma unroll
        for (int i = 0; i < 8; i++) {
            unsigned hi = f2tf32(rb[i]);
            float lo = rb[i] - __uint_as_float(hi);
            sm[OFF_BH + bi[i]] = __uint_as_float(hi);
            sm[OFF_BL + bi[i]] = __uint_as_float(f2tf32(lo));
        }
    }
    __syncthreads();

    int buf = 0;
    for (int it = 0; it < NIT; it++) {
        bool has_next = (it + 1 < NIT);
        // ---- prefetch next tile into registers ----
        if (has_next) {
            int k0 = (it + 1) * GBK;
            bool k_full = (k0 + GBK <= K);
            if (m_full && k_full) {
                const float* p = &A[(m0 + a_m) * K + k0 + a_k];
                float4 v0 = *(const float4*)p;
                float4 v1 = *(const float4*)(p + 4);
                ra[0] = v0.x; ra[1] = v0.y; ra[2] = v0.z; ra[3] = v0.w;
                ra[4] = v1.x; ra[5] = v1.y; ra[6] = v1.z; ra[7] = v1.w;
            } else {
#pragma unroll
                for (int i = 0; i < 8; i++) {
                    int gm = m0 + a_m, gk = k0 + a_k + i;
                    ra[i] = (gm < M && gk < K) ? A[gm * K + gk] : 0.f;
                }
            }
            if (n_full && k_full) {
                const float* p = &B[(k0 + b_k) * N + n0 + b_n];
                float4 v0 = *(const float4*)p;
                float4 v1 = *(const float4*)(p + 4);
                rb[0] = v0.x; rb[1] = v0.y; rb[2] = v0.z; rb[3] = v0.w;
                rb[4] = v1.x; rb[5] = v1.y; rb[6] = v1.z; rb[7] = v1.w;
            } else {
#pragma unroll
                for (int i = 0; i < 8; i++) {
                    int gk = k0 + b_k, gn = n0 + b_n + i;
                    rb[i] = (gk < K && gn < N) ? B[gk * N + gn] : 0.f;
                }
            }
        }

        // ---- compute on current buffer (vectorized fragment loads) ----
        const float* base = sm + buf * BUF_FLOATS;
#pragma unroll
        for (int s = 0; s < 2; s++) {
            float4 ah[2], al[2];
#pragma unroll
            for (int i = 0; i < 2; i++) {
                int mt = (wm >> 4) + i;
                int fo = ((s * 8 + mt) * 32 + lane) * 4;
                ah[i] = *(const float4*)(base + OFF_AH + fo);
                al[i] = *(const float4*)(base + OFF_AL + fo);
            }
#pragma unroll
            for (int j = 0; j < 8; j++) {
                int nt = (wn >> 3) + j;
                int fo = ((s * 16 + nt) * 32 + lane) * 2;
                float2 bh = *(const float2*)(base + OFF_BH + fo);
                float2 bl = *(const float2*)(base + OFF_BL + fo);
#pragma unroll
                for (int i = 0; i < 2; i++) {
                    mma_tf32(acc[i][j], ah[i], bh.x, bh.y);
                    mma_tf32(acc[i][j], ah[i], bl.x, bl.y);
                    mma_tf32(acc[i][j], al[i], bh.x, bh.y);
                }
            }
        }

        // ---- convert + STS next tile into other buffer ----
        if (has_next) {
            float* ob = sm + (buf ^ 1) * BUF_FLOATS;
#pragma unroll
            for (int i = 0; i < 8; i++) {
                unsigned hi = f2tf32(ra[i]);
                float lo = ra[i] - __uint_as_float(hi);
                ob[OFF_AH + ai[i]] = __uint_as_float(hi);
                ob[OFF_AL + ai[i]] = __uint_as_float(f2tf32(lo));
            }
#pragma unroll
            for (int i = 0; i < 8; i++) {
                unsigned hi = f2tf32(rb[i]);
                float lo = rb[i] - __uint_as_float(hi);
                ob[OFF_BH + bi[i]] = __uint_as_float(hi);
                ob[OFF_BL + bi[i]] = __uint_as_float(f2tf32(lo));
            }
        }
        __syncthreads();
        buf ^= 1;
    }

    // ---- epilogue: bias + optional relu ----
#pragma unroll
    for (int i = 0; i < 2; i++) {
#pragma unroll
        for (int c = 0; c < 4; c++) {
            int row = m0 + wm + i * 16 + lq + ((c >= 2) ? 8 : 0);
            if (row >= M) continue;
#pragma unroll
            for (int j = 0; j < 8; j++) {
                int col = n0 + wn + j * 8 + 2 * lr + (c & 1);
                if (col >= N) continue;
                float v = acc[i][j][c] + bias[col];
                if (relu) v = fmaxf(v, 0.f);
                C[row * N + col] = v;
            }
        }
    }
}

// ---------------- host orchestration ---------------------------------------
static inline void sgemm(int M, int N, int K, const float* A, const float* B,
                         const float* bias, float* C, int relu) {
    dim3 grid((N + BN - 1) / BN, (M + BM - 1) / BM);
    k_sgemm<<<grid, 256>>>(M, N, K, A, B, bias, C, relu);
}

static inline void gemm_tf32(int M, int N, int K, const float* A, const float* B,
                             const float* bias, float* C, int relu) {
    dim3 grid((N + GBN - 1) / GBN, (M + GBM - 1) / GBM);
    k_gemm_tf32<<<grid, 256, GSM_TOTAL_BYTES>>>(M, N, K, A, B, bias, C, relu);
}

extern "C" void kernel_launch(void* const* d_in, const int* in_sizes, int n_in,
                              void* d_out, int out_size) {
    const float* x      = (const float*)d_in[0];
    const void*  edges  = d_in[1];
    const void*  batch  = d_in[2];
    const float* w1_0 = (const float*)d_in[3];
    const float* b1_0 = (const float*)d_in[4];
    const float* w2_0 = (const float*)d_in[5];
    const float* b2_0 = (const float*)d_in[6];
    const float* w1_r = (const float*)d_in[7];
    const float* b1_r = (const float*)d_in[8];
    const float* w2_r = (const float*)d_in[9];
    const float* b2_r = (const float*)d_in[10];
    const float* cw1  = (const float*)d_in[11];
    const float* cb1  = (const float*)d_in[12];
    const float* cw2  = (const float*)d_in[13];
    const float* cb2  = (const float*)d_in[14];
    const float* cw3  = (const float*)d_in[15];
    const float* cb3  = (const float*)d_in[16];
    float* out = (float*)d_out;

    float *h, *agg, *t1, *feats, *z1, *z2;
    int *src, *dst, *bat, *deg, *rowptr, *cursor, *col;
    cudaGetSymbolAddress((void**)&h, g_h);
    cudaGetSymbolAddress((void**)&agg, g_agg);
    cudaGetSymbolAddress((void**)&t1, g_t1);
    cudaGetSymbolAddress((void**)&feats, g_feats);
    cudaGetSymbolAddress((void**)&z1, g_z1);
    cudaGetSymbolAddress((void**)&z2, g_z2);
    cudaGetSymbolAddress((void**)&src, g_src);
    cudaGetSymbolAddress((void**)&dst, g_dst);
    cudaGetSymbolAddress((void**)&bat, g_batch);
    cudaGetSymbolAddress((void**)&deg, g_deg);
    cudaGetSymbolAddress((void**)&rowptr, g_rowptr);
    cudaGetSymbolAddress((void**)&cursor, g_cursor);
    cudaGetSymbolAddress((void**)&col, g_col);

    // allow 64 KB dynamic smem for the tf32 GEMM
    cudaFuncSetAttribute(k_gemm_tf32, cudaFuncAttributeMaxDynamicSharedMemorySize,
                         GSM_TOTAL_BYTES);

    // 1) index dtype detect + convert
    k_detect<<<1, 32>>>((const unsigned long long*)edges);
    {
        int n = (EE > NN) ? EE : NN;
        k_convert<<<(n + 255) / 256, 256>>>(edges, batch);
    }

    // 2) CSR build (dst-major, col = src)
    k_zero_int<<<(NN + 255) / 256, 256>>>(deg, NN);
    k_count<<<(EE + 255) / 256, 256>>>(dst, deg);
    k_scan<<<1, 1024>>>(deg, rowptr, NN);
    k_copy_int<<<(NN + 255) / 256, 256>>>(rowptr, cursor, NN);
    k_fill<<<(EE + 255) / 256, 256>>>(src, dst, cursor, col);

    // 3) layer 0 (input width 9) — FFMA path for K=9
    k_aggregate<<<NN, 32>>>(x, agg, rowptr, col, INF);
    sgemm(NN, HID, INF, agg, w1_0, b1_0, t1, 1);
    gemm_tf32(NN, HID, HID, t1, w2_0, b2_0, h, 1);  // fused inter-layer relu

    // 4) layers 1..4 — tensor-core GEMMs
    for (int i = 0; i < 4; i++) {
        k_aggregate_v4<<<NN, 160>>>(h, agg, rowptr, col);
        gemm_tf32(NN, HID, HID, agg, w1_r + i * HID * HID, b1_r + i * HID, t1, 1);
        gemm_tf32(NN, HID, HID, t1, w2_r + i * HID * HID, b2_r + i * HID, h, (i < 3) ? 1 : 0);
    }

    // 5) global_add_pool
    k_zero_float<<<(NG * HID + 255) / 256, 256>>>(feats, NG * HID);
    k_pool<<<(NN * HID + 255) / 256, 256>>>(h, bat, feats);

    // 6) classifier MLP (small — FFMA path)
    sgemm(NG, CHID, HID, feats, cw1, cb1, z1, 1);
    sgemm(NG, CHID, CHID, z1, cw2, cb2, z2, 1);
    sgemm(NG, NT, CHID, z2, cw3, cb3, out, 0);
}

// round 10
// speedup vs baseline: 1.9827x; 1.9827x over previous
#include <cuda_runtime.h>
#include <cstdint>

// Problem constants (match reference)
#define NN   30000
#define EE   300000
#define NG   512
#define HID  600
#define INF  9
#define NT   128
#define CHID 256

// ---------------- device scratch (allocation-free rule: device globals) ----
__device__ float g_h[NN * HID];
__device__ float g_agg[NN * HID];
__device__ float g_t1[NN * HID];
__device__ float g_feats[NG * HID];
__device__ float g_z1[NG * CHID];
__device__ float g_z2[NG * CHID];

__device__ int g_src[EE];
__device__ int g_dst[EE];
__device__ int g_batch[NN];
__device__ int g_deg[NN];
__device__ int g_rowptr[NN + 1];
__device__ int g_cursor[NN];
__device__ int g_col[EE];
__device__ int g_is64;

// ---------------- index dtype detection + conversion ----------------------
__global__ void k_detect(const unsigned long long* __restrict__ p) {
    if (threadIdx.x == 0 && blockIdx.x == 0) {
        int is64 = 1;
        for (int i = 0; i < 256; i++)
            if (p[i] >> 32) { is64 = 0; break; }
        g_is64 = is64;
    }
}

__global__ void k_convert(const void* __restrict__ edges,
                          const void* __restrict__ batch) {
    int i = blockIdx.x * blockDim.x + threadIdx.x;
    int is64 = g_is64;
    if (i < EE) {
        if (is64) {
            const long long* p = (const long long*)edges;
            g_src[i] = (int)p[i];
            g_dst[i] = (int)p[EE + i];
        } else {
            const int* p = (const int*)edges;
            g_src[i] = p[i];
            g_dst[i] = p[EE + i];
        }
    }
    if (i < NN) {
        if (is64) {
            const long long* p = (const long long*)batch;
            g_batch[i] = (int)p[i];
        } else {
            const int* p = (const int*)batch;
            g_batch[i] = p[i];
        }
    }
}

// ---------------- small utility kernels ------------------------------------
__global__ void k_zero_int(int* p, int n) {
    int i = blockIdx.x * blockDim.x + threadIdx.x;
    if (i < n) p[i] = 0;
}
__global__ void k_zero_float(float* p, int n) {
    int i = blockIdx.x * blockDim.x + threadIdx.x;
    if (i < n) p[i] = 0.f;
}
__global__ void k_copy_int(const int* __restrict__ a, int* __restrict__ b, int n) {
    int i = blockIdx.x * blockDim.x + threadIdx.x;
    if (i < n) b[i] = a[i];
}

// ---------------- CSR build (dst-major) ------------------------------------
__global__ void k_count(const int* __restrict__ dst, int* __restrict__ deg) {
    int i = blockIdx.x * blockDim.x + threadIdx.x;
    if (i < EE) atomicAdd(&deg[dst[i]], 1);
}

__global__ void k_scan(const int* __restrict__ in, int* __restrict__ out, int n) {
    __shared__ int s[1024];
    __shared__ int s_carry;
    int tid = threadIdx.x;
    if (tid == 0) s_carry = 0;
    __syncthreads();
    for (int base = 0; base < n; base += 1024) {
        int i = base + tid;
        int v = (i < n) ? in[i] : 0;
        s[tid] = v;
        __syncthreads();
        for (int off = 1; off < 1024; off <<= 1) {
            int t = (tid >= off) ? s[tid - off] : 0;
            __syncthreads();
            s[tid] += t;
            __syncthreads();
        }
        int c = s_carry;
        if (i < n) out[i] = c + s[tid] - v;
        __syncthreads();
        if (tid == 0) s_carry = c + s[1023];
        __syncthreads();
    }
    if (tid == 0) out[n] = s_carry;
}

__global__ void k_fill(const int* __restrict__ src, const int* __restrict__ dst,
                       int* __restrict__ cursor, int* __restrict__ col) {
    int i = blockIdx.x * blockDim.x + threadIdx.x;
    if (i < EE) {
        int p = atomicAdd(&cursor[dst[i]], 1);
        col[p] = src[i];
    }
}

// ---------------- aggregation --------------------------------------------
__global__ void k_aggregate(const float* __restrict__ h, float* __restrict__ agg,
                            const int* __restrict__ rowptr,
                            const int* __restrict__ col, int width) {
    __shared__ int s_nbr[64];
    int node = blockIdx.x;
    int f = threadIdx.x;
    int CH = (blockDim.x < 64) ? blockDim.x : 64;
    int start = rowptr[node], end = rowptr[node + 1];
    float acc = (f < width) ? h[node * width + f] : 0.f;
    for (int base = start; base < end; base += CH) {
        int cnt = end - base;
        if (cnt > CH) cnt = CH;
        if ((int)threadIdx.x < cnt) s_nbr[threadIdx.x] = col[base + threadIdx.x];
        __syncthreads();
        if (f < width) {
            for (int j = 0; j < cnt; j++)
                acc += h[s_nbr[j] * width + f];
        }
        __syncthreads();
    }
    if (f < width) agg[node * width + f] = acc;
}

__global__ void k_aggregate_v4(const float* __restrict__ h, float* __restrict__ agg,
                               const int* __restrict__ rowptr,
                               const int* __restrict__ col) {
    __shared__ int s_nbr[32];
    int node = blockIdx.x;
    int f4 = threadIdx.x;                  // 0..159, use first 150
    int start = rowptr[node], end = rowptr[node + 1];
    const float4* hv = (const float4*)h;
    float4 acc;
    if (f4 < 150) acc = hv[node * 150 + f4];
    else acc = make_float4(0.f, 0.f, 0.f, 0.f);
    for (int base = start; base < end; base += 32) {
        int cnt = end - base;
        if (cnt > 32) cnt = 32;
        if ((int)threadIdx.x < cnt) s_nbr[threadIdx.x] = col[base + threadIdx.x];
        __syncthreads();
        if (f4 < 150) {
            for (int j = 0; j < cnt; j++) {
                float4 v = hv[s_nbr[j] * 150 + f4];
                acc.x += v.x; acc.y += v.y; acc.z += v.z; acc.w += v.w;
            }
        }
        __syncthreads();
    }
    if (f4 < 150) ((float4*)agg)[node * 150 + f4] = acc;
}

// ---------------- pooling --------------------------------------------------
__global__ void k_pool(const float* __restrict__ h, const int* __restrict__ batch,
                       float* __restrict__ feats) {
    int idx = blockIdx.x * blockDim.x + threadIdx.x;
    if (idx >= NN * HID) return;
    int n = idx / HID;
    int f = idx - n * HID;
    atomicAdd(&feats[batch[n] * HID + f], h[idx]);
}

// ---------------- FFMA SGEMM (small GEMMs: K=9 layer0, classifier) ---------
#define BM 128
#define BN 128
#define BK 8

__global__ __launch_bounds__(256)
void k_sgemm(int M, int N, int K,
             const float* __restrict__ A, const float* __restrict__ B,
             const float* __restrict__ bias, float* __restrict__ C, int relu) {
    __shared__ float As[BK][BM + 4];
    __shared__ float Bs[BK][BN];

    int tid = threadIdx.x;
    int tx = tid & 15;
    int ty = tid >> 4;
    int m0 = blockIdx.y * BM;
    int n0 = blockIdx.x * BN;

    float acc[8][8];
#pragma unroll
    for (int i = 0; i < 8; i++)
#pragma unroll
        for (int j = 0; j < 8; j++) acc[i][j] = 0.f;

    for (int k0 = 0; k0 < K; k0 += BK) {
#pragma unroll
        for (int i = 0; i < 4; i++) {
            int e = tid * 4 + i;
            int m = e >> 3, k = e & 7;
            int gm = m0 + m, gk = k0 + k;
            As[k][m] = (gm < M && gk < K) ? A[gm * K + gk] : 0.f;
        }
#pragma unroll
        for (int i = 0; i < 4; i++) {
            int e = tid * 4 + i;
            int k = e >> 7, n = e & 127;
            int gn = n0 + n, gk = k0 + k;
            Bs[k][n] = (gn < N && gk < K) ? B[gk * N + gn] : 0.f;
        }
        __syncthreads();

#pragma unroll
        for (int k = 0; k < BK; k++) {
            float4 a0 = *(const float4*)&As[k][ty * 4];
            float4 a1 = *(const float4*)&As[k][64 + ty * 4];
            float4 b0 = *(const float4*)&Bs[k][tx * 4];
            float4 b1 = *(const float4*)&Bs[k][64 + tx * 4];
            float a[8] = {a0.x, a0.y, a0.z, a0.w, a1.x, a1.y, a1.z, a1.w};
            float b[8] = {b0.x, b0.y, b0.z, b0.w, b1.x, b1.y, b1.z, b1.w};
#pragma unroll
            for (int i = 0; i < 8; i++)
#pragma unroll
                for (int j = 0; j < 8; j++)
                    acc[i][j] = fmaf(a[i], b[j], acc[i][j]);
        }
        __syncthreads();
    }

#pragma unroll
    for (int i = 0; i < 8; i++) {
        int r = (i < 4) ? (ty * 4 + i) : (64 + ty * 4 + (i - 4));
        int gm = m0 + r;
        if (gm >= M) continue;
#pragma unroll
        for (int j = 0; j < 8; j++) {
            int c = (j < 4) ? (tx * 4 + j) : (64 + tx * 4 + (j - 4));
            int gn = n0 + c;
            if (gn >= N) continue;
            float v = acc[i][j] + bias[gn];
            if (relu) v = fmaxf(v, 0.f);
            C[gm * N + gn] = v;
        }
    }
}

// ---------------- 3xFP16 mma.sync GEMM (hi/lo split, no cuda_fp16.h) -------
// C = act(A[M,K] @ B[K,N] + bias), fp32 in/out.
// a = hi + lo in fp16 (hi = rn(a), lo = rn(a-hi)); product via 3 passes
// (hi*hi + hi*lo + lo*hi) with fp32 accumulate; dropped lo*lo ~ 2^-22.
// 128x128x16 block tile, 256 threads (8 warps as 4x2, warp tile 32x64).
// smem holds PACKED (hi|lo<<16) words in [k][m]/[k][n] layout, stride 132
// -> fragment LDS conflict-free; fragment regs built with one PRMT each.
#define GBM 128
#define GBN 128
#define GBK 16
#define AST 132                       // padded stride (words)
#define TILEW (GBK * AST)             // 2112 words per operand tile

// fp16 conversions via PTX (avoids cuda_fp16.h)
__device__ __forceinline__ uint32_t pack_h2(float v) {
    unsigned short hi, lo;
    float vhi;
    asm("cvt.rn.f16.f32 %0, %1;" : "=h"(hi) : "f"(v));
    asm("cvt.f32.f16 %0, %1;" : "=f"(vhi) : "h"(hi));
    float r = v - vhi;
    asm("cvt.rn.f16.f32 %0, %1;" : "=h"(lo) : "f"(r));
    return (uint32_t)hi | ((uint32_t)lo << 16);
}

__device__ __forceinline__ void mma_f16(float* d, const uint32_t* a,
                                        uint32_t b0, uint32_t b1) {
    asm volatile(
        "mma.sync.aligned.m16n8k16.row.col.f32.f16.f16.f32 "
        "{%0,%1,%2,%3}, {%4,%5,%6,%7}, {%8,%9}, {%0,%1,%2,%3};\n"
        : "+f"(d[0]), "+f"(d[1]), "+f"(d[2]), "+f"(d[3])
        : "r"(a[0]), "r"(a[1]), "r"(a[2]), "r"(a[3]), "r"(b0), "r"(b1));
}

__global__ __launch_bounds__(256, 1)
void k_gemm_f16(int M, int N, int K,
                const float* __restrict__ A, const float* __restrict__ B,
                const float* __restrict__ bias, float* __restrict__ C, int relu) {
    __shared__ uint32_t shA[2][TILEW];
    __shared__ uint32_t shB[2][TILEW];

    int tid = threadIdx.x;
    int lane = tid & 31;
    int warp = tid >> 5;
    int wm = (warp >> 1) * 32;   // warp row offset in tile
    int wn = (warp & 1) * 64;    // warp col offset in tile
    int lq = lane >> 2;          // 0..7
    int lr = lane & 3;           // 0..3
    int c0 = lr * 2;             // fragment k base

    int m0 = blockIdx.y * GBM;
    int n0 = blockIdx.x * GBN;

    // loader mappings
    int am = tid >> 1;            // A row 0..127
    int ak = (tid & 1) * 8;       // A k offset 0/8
    int bk = tid >> 4;            // B k row 0..15
    int bq = tid & 15;            // B n base (stride-16 interleave)
    int gmA = m0 + am;
    bool a_ok = (gmA < M);

    float acc[2][8][4];
#pragma unroll
    for (int i = 0; i < 2; i++)
#pragma unroll
        for (int j = 0; j < 8; j++)
#pragma unroll
            for (int c = 0; c < 4; c++) acc[i][j][c] = 0.f;

    float ra[8], rb[8];
    int NIT = (K + GBK - 1) / GBK;

    // ---- prologue: load + convert + STS tile 0 ----
    {
        if (a_ok && (ak + 8 <= K)) {
            const float* p = &A[gmA * K + ak];
            float4 v0 = *(const float4*)p;
            float4 v1 = *(const float4*)(p + 4);
            ra[0] = v0.x; ra[1] = v0.y; ra[2] = v0.z; ra[3] = v0.w;
            ra[4] = v1.x; ra[5] = v1.y; ra[6] = v1.z; ra[7] = v1.w;
        } else {
#pragma unroll
            for (int i = 0; i < 8; i++) {
                int gk = ak + i;
                ra[i] = (a_ok && gk < K) ? A[gmA * K + gk] : 0.f;
            }
        }
        bool k_ok = (bk < K);
#pragma unroll
        for (int i = 0; i < 8; i++) {
            int gn = n0 + bq + 16 * i;
            rb[i] = (k_ok && gn < N) ? B[bk * N + gn] : 0.f;
        }
#pragma unroll
        for (int i = 0; i < 8; i++)
            shA[0][(ak + i) * AST + am] = pack_h2(ra[i]);
#pragma unroll
        for (int i = 0; i < 8; i++)
            shB[0][bk * AST + bq + 16 * i] = pack_h2(rb[i]);
    }
    __syncthreads();

    int buf = 0;
    for (int it = 0; it < NIT; it++) {
        bool has_next = (it + 1 < NIT);
        // ---- prefetch next tile into registers ----
        if (has_next) {
            int k0 = (it + 1) * GBK;
            if (a_ok && (k0 + ak + 8 <= K)) {
                const float* p = &A[gmA * K + k0 + ak];
                float4 v0 = *(const float4*)p;
                float4 v1 = *(const float4*)(p + 4);
                ra[0] = v0.x; ra[1] = v0.y; ra[2] = v0.z; ra[3] = v0.w;
                ra[4] = v1.x; ra[5] = v1.y; ra[6] = v1.z; ra[7] = v1.w;
            } else {
#pragma unroll
                for (int i = 0; i < 8; i++) {
                    int gk = k0 + ak + i;
                    ra[i] = (a_ok && gk < K) ? A[gmA * K + gk] : 0.f;
                }
            }
            int gk = k0 + bk;
            bool k_ok = (gk < K);
#pragma unroll
            for (int i = 0; i < 8; i++) {
                int gn = n0 + bq + 16 * i;
                rb[i] = (k_ok && gn < N) ? B[gk * N + gn] : 0.f;
            }
        }

        // ---- compute on current buffer ----
        const uint32_t* bA = shA[buf];
        const uint32_t* bB = shB[buf];
        uint32_t ah[2][4], al[2][4];
#pragma unroll
        for (int i = 0; i < 2; i++) {
            int r1 = wm + i * 16 + lq;
            uint32_t w00 = bA[c0 * AST + r1];
            uint32_t w01 = bA[(c0 + 1) * AST + r1];
            uint32_t w10 = bA[c0 * AST + r1 + 8];
            uint32_t w11 = bA[(c0 + 1) * AST + r1 + 8];
            uint32_t w20 = bA[(c0 + 8) * AST + r1];
            uint32_t w21 = bA[(c0 + 9) * AST + r1];
            uint32_t w30 = bA[(c0 + 8) * AST + r1 + 8];
            uint32_t w31 = bA[(c0 + 9) * AST + r1 + 8];
            ah[i][0] = __byte_perm(w00, w01, 0x5410);
            al[i][0] = __byte_perm(w00, w01, 0x7632);
            ah[i][1] = __byte_perm(w10, w11, 0x5410);
            al[i][1] = __byte_perm(w10, w11, 0x7632);
            ah[i][2] = __byte_perm(w20, w21, 0x5410);
            al[i][2] = __byte_perm(w20, w21, 0x7632);
            ah[i][3] = __byte_perm(w30, w31, 0x5410);
            al[i][3] = __byte_perm(w30, w31, 0x7632);
        }
#pragma unroll
        for (int j = 0; j < 8; j++) {
            int n = wn + j * 8 + lq;
            uint32_t u0 = bB[c0 * AST + n];
            uint32_t u1 = bB[(c0 + 1) * AST + n];
            uint32_t u2 = bB[(c0 + 8) * AST + n];
            uint32_t u3 = bB[(c0 + 9) * AST + n];
            uint32_t bh0 = __byte_perm(u0, u1, 0x5410);
            uint32_t bl0 = __byte_perm(u0, u1, 0x7632);
            uint32_t bh1 = __byte_perm(u2, u3, 0x5410);
            uint32_t bl1 = __byte_perm(u2, u3, 0x7632);
#pragma unroll
            for (int i = 0; i < 2; i++) {
                mma_f16(acc[i][j], ah[i], bh0, bh1);
                mma_f16(acc[i][j], ah[i], bl0, bl1);
                mma_f16(acc[i][j], al[i], bh0, bh1);
            }
        }

        // ---- convert + STS next tile into other buffer ----
        if (has_next) {
            int ob = buf ^ 1;
#pragma unroll
            for (int i = 0; i < 8; i++)
                shA[ob][(ak + i) * AST + am] = pack_h2(ra[i]);
#pragma unroll
            for (int i = 0; i < 8; i++)
                shB[ob][bk * AST + bq + 16 * i] = pack_h2(rb[i]);
        }
        __syncthreads();
        buf ^= 1;
    }

    // ---- epilogue: bias + optional relu ----
#pragma unroll
    for (int i = 0; i < 2; i++) {
#pragma unroll
        for (int c = 0; c < 4; c++) {
            int row = m0 + wm + i * 16 + lq + ((c >= 2) ? 8 : 0);
            if (row >= M) continue;
#pragma unroll
            for (int j = 0; j < 8; j++) {
                int col = n0 + wn + j * 8 + 2 * lr + (c & 1);
                if (col >= N) continue;
                float v = acc[i][j][c] + bias[col];
                if (relu) v = fmaxf(v, 0.f);
                C[row * N + col] = v;
            }
        }
    }
}

// ---------------- host orchestration ---------------------------------------
static inline void sgemm(int M, int N, int K, const float* A, const float* B,
                         const float* bias, float* C, int relu) {
    dim3 grid((N + BN - 1) / BN, (M + BM - 1) / BM);
    k_sgemm<<<grid, 256>>>(M, N, K, A, B, bias, C, relu);
}

static inline void gemm_f16(int M, int N, int K, const float* A, const float* B,
                            const float* bias, float* C, int relu) {
    dim3 grid((N + GBN - 1) / GBN, (M + GBM - 1) / GBM);
    k_gemm_f16<<<grid, 256>>>(M, N, K, A, B, bias, C, relu);
}

extern "C" void kernel_launch(void* const* d_in, const int* in_sizes, int n_in,
                              void* d_out, int out_size) {
    const float* x      = (const float*)d_in[0];
    const void*  edges  = d_in[1];
    const void*  batch  = d_in[2];
    const float* w1_0 = (const float*)d_in[3];
    const float* b1_0 = (const float*)d_in[4];
    const float* w2_0 = (const float*)d_in[5];
    const float* b2_0 = (const float*)d_in[6];
    const float* w1_r = (const float*)d_in[7];
    const float* b1_r = (const float*)d_in[8];
    const float* w2_r = (const float*)d_in[9];
    const float* b2_r = (const float*)d_in[10];
    const float* cw1  = (const float*)d_in[11];
    const float* cb1  = (const float*)d_in[12];
    const float* cw2  = (const float*)d_in[13];
    const float* cb2  = (const float*)d_in[14];
    const float* cw3  = (const float*)d_in[15];
    const float* cb3  = (const float*)d_in[16];
    float* out = (float*)d_out;

    float *h, *agg, *t1, *feats, *z1, *z2;
    int *src, *dst, *bat, *deg, *rowptr, *cursor, *col;
    cudaGetSymbolAddress((void**)&h, g_h);
    cudaGetSymbolAddress((void**)&agg, g_agg);
    cudaGetSymbolAddress((void**)&t1, g_t1);
    cudaGetSymbolAddress((void**)&feats, g_feats);
    cudaGetSymbolAddress((void**)&z1, g_z1);
    cudaGetSymbolAddress((void**)&z2, g_z2);
    cudaGetSymbolAddress((void**)&src, g_src);
    cudaGetSymbolAddress((void**)&dst, g_dst);
    cudaGetSymbolAddress((void**)&bat, g_batch);
    cudaGetSymbolAddress((void**)&deg, g_deg);
    cudaGetSymbolAddress((void**)&rowptr, g_rowptr);
    cudaGetSymbolAddress((void**)&cursor, g_cursor);
    cudaGetSymbolAddress((void**)&col, g_col);

    // 1) index dtype detect + convert
    k_detect<<<1, 32>>>((const unsigned long long*)edges);
    {
        int n = (EE > NN) ? EE : NN;
        k_convert<<<(n + 255) / 256, 256>>>(edges, batch);
    }

    // 2) CSR build (dst-major, col = src)
    k_zero_int<<<(NN + 255) / 256, 256>>>(deg, NN);
    k_count<<<(EE + 255) / 256, 256>>>(dst, deg);
    k_scan<<<1, 1024>>>(deg, rowptr, NN);
    k_copy_int<<<(NN + 255) / 256, 256>>>(rowptr, cursor, NN);
    k_fill<<<(EE + 255) / 256, 256>>>(src, dst, cursor, col);

    // 3) layer 0 (input width 9) — FFMA path for K=9
    k_aggregate<<<NN, 32>>>(x, agg, rowptr, col, INF);
    sgemm(NN, HID, INF, agg, w1_0, b1_0, t1, 1);
    gemm_f16(NN, HID, HID, t1, w2_0, b2_0, h, 1);  // fused inter-layer relu

    // 4) layers 1..4 — tensor-core GEMMs
    for (int i = 0; i < 4; i++) {
        k_aggregate_v4<<<NN, 160>>>(h, agg, rowptr, col);
        gemm_f16(NN, HID, HID, agg, w1_r + i * HID * HID, b1_r + i * HID, t1, 1);
        gemm_f16(NN, HID, HID, t1, w2_r + i * HID * HID, b2_r + i * HID, h, (i < 3) ? 1 : 0);
    }

    // 5) global_add_pool
    k_zero_float<<<(NG * HID + 255) / 256, 256>>>(feats, NG * HID);
    k_pool<<<(NN * HID + 255) / 256, 256>>>(h, bat, feats);

    // 6) classifier MLP (small — FFMA path)
    sgemm(NG, CHID, HID, feats, cw1, cb1, z1, 1);
    sgemm(NG, CHID, CHID, z1, cw2, cb2, z2, 1);
    sgemm(NG, NT, CHID, z2, cw3, cb3, out, 0);
}

// round 11
// speedup vs baseline: 2.0859x; 1.0521x over previous
#include <cuda_runtime.h>
#include <cstdint>

// Problem constants (match reference)
#define NN   30000
#define EE   300000
#define NG   512
#define HID  600
#define INF  9
#define NT   128
#define CHID 256

// ---------------- device scratch (allocation-free rule: device globals) ----
__device__ float g_h[NN * HID];
__device__ float g_agg[NN * HID];
__device__ float g_t1[NN * HID];
__device__ float g_feats[NG * HID];
__device__ float g_z1[NG * CHID];
__device__ float g_z2[NG * CHID];

__device__ int g_src[EE];
__device__ int g_dst[EE];
__device__ int g_batch[NN];
__device__ int g_deg[NN];
__device__ int g_rowptr[NN + 1];
__device__ int g_cursor[NN];
__device__ int g_col[EE];
__device__ int g_gptr[NG + 1];
__device__ int g_is64;

// ---------------- index dtype detection + conversion ----------------------
__global__ void k_detect(const unsigned long long* __restrict__ p) {
    if (threadIdx.x == 0 && blockIdx.x == 0) {
        int is64 = 1;
        for (int i = 0; i < 256; i++)
            if (p[i] >> 32) { is64 = 0; break; }
        g_is64 = is64;
    }
}

__global__ void k_convert(const void* __restrict__ edges,
                          const void* __restrict__ batch) {
    int i = blockIdx.x * blockDim.x + threadIdx.x;
    int is64 = g_is64;
    if (i < EE) {
        if (is64) {
            const long long* p = (const long long*)edges;
            g_src[i] = (int)p[i];
            g_dst[i] = (int)p[EE + i];
        } else {
            const int* p = (const int*)edges;
            g_src[i] = p[i];
            g_dst[i] = p[EE + i];
        }
    }
    if (i < NN) {
        if (is64) {
            const long long* p = (const long long*)batch;
            g_batch[i] = (int)p[i];
        } else {
            const int* p = (const int*)batch;
            g_batch[i] = p[i];
        }
    }
}

// ---------------- small utility kernels ------------------------------------
__global__ void k_zero_int(int* p, int n) {
    int i = blockIdx.x * blockDim.x + threadIdx.x;
    if (i < n) p[i] = 0;
}
__global__ void k_copy_int(const int* __restrict__ a, int* __restrict__ b, int n) {
    int i = blockIdx.x * blockDim.x + threadIdx.x;
    if (i < n) b[i] = a[i];
}

// ---------------- CSR build (dst-major) ------------------------------------
__global__ void k_count(const int* __restrict__ dst, int* __restrict__ deg) {
    int i = blockIdx.x * blockDim.x + threadIdx.x;
    if (i < EE) atomicAdd(&deg[dst[i]], 1);
}

__global__ void k_scan(const int* __restrict__ in, int* __restrict__ out, int n) {
    __shared__ int s[1024];
    __shared__ int s_carry;
    int tid = threadIdx.x;
    if (tid == 0) s_carry = 0;
    __syncthreads();
    for (int base = 0; base < n; base += 1024) {
        int i = base + tid;
        int v = (i < n) ? in[i] : 0;
        s[tid] = v;
        __syncthreads();
        for (int off = 1; off < 1024; off <<= 1) {
            int t = (tid >= off) ? s[tid - off] : 0;
            __syncthreads();
            s[tid] += t;
            __syncthreads();
        }
        int c = s_carry;
        if (i < n) out[i] = c + s[tid] - v;
        __syncthreads();
        if (tid == 0) s_carry = c + s[1023];
        __syncthreads();
    }
    if (tid == 0) out[n] = s_carry;
}

__global__ void k_fill(const int* __restrict__ src, const int* __restrict__ dst,
                       int* __restrict__ cursor, int* __restrict__ col) {
    int i = blockIdx.x * blockDim.x + threadIdx.x;
    if (i < EE) {
        int p = atomicAdd(&cursor[dst[i]], 1);
        col[p] = src[i];
    }
}

// ---------------- graph ranges (batch_ind is sorted) -----------------------
__global__ void k_gptr(const int* __restrict__ batch, int* __restrict__ gptr) {
    int g = blockIdx.x * blockDim.x + threadIdx.x;
    if (g > NG) return;
    // lower bound: first i with batch[i] >= g
    int lo = 0, hi = NN;
    while (lo < hi) {
        int mid = (lo + hi) >> 1;
        if (batch[mid] < g) lo = mid + 1; else hi = mid;
    }
    gptr[g] = lo;
}

// ---------------- aggregation --------------------------------------------
__global__ void k_aggregate(const float* __restrict__ h, float* __restrict__ agg,
                            const int* __restrict__ rowptr,
                            const int* __restrict__ col, int width) {
    __shared__ int s_nbr[64];
    int node = blockIdx.x;
    int f = threadIdx.x;
    int CH = (blockDim.x < 64) ? blockDim.x : 64;
    int start = rowptr[node], end = rowptr[node + 1];
    float acc = (f < width) ? h[node * width + f] : 0.f;
    for (int base = start; base < end; base += CH) {
        int cnt = end - base;
        if (cnt > CH) cnt = CH;
        if ((int)threadIdx.x < cnt) s_nbr[threadIdx.x] = col[base + threadIdx.x];
        __syncthreads();
        if (f < width) {
            for (int j = 0; j < cnt; j++)
                acc += h[s_nbr[j] * width + f];
        }
        __syncthreads();
    }
    if (f < width) agg[node * width + f] = acc;
}

__global__ void k_aggregate_v4(const float* __restrict__ h, float* __restrict__ agg,
                               const int* __restrict__ rowptr,
                               const int* __restrict__ col) {
    __shared__ int s_nbr[32];
    int node = blockIdx.x;
    int f4 = threadIdx.x;                  // 0..159, use first 150
    int start = rowptr[node], end = rowptr[node + 1];
    const float4* hv = (const float4*)h;
    float4 acc;
    if (f4 < 150) acc = hv[node * 150 + f4];
    else acc = make_float4(0.f, 0.f, 0.f, 0.f);
    for (int base = start; base < end; base += 32) {
        int cnt = end - base;
        if (cnt > 32) cnt = 32;
        if ((int)threadIdx.x < cnt) s_nbr[threadIdx.x] = col[base + threadIdx.x];
        __syncthreads();
        if (f4 < 150) {
            for (int j = 0; j < cnt; j++) {
                float4 v = hv[s_nbr[j] * 150 + f4];
                acc.x += v.x; acc.y += v.y; acc.z += v.z; acc.w += v.w;
            }
        }
        __syncthreads();
    }
    if (f4 < 150) ((float4*)agg)[node * 150 + f4] = acc;
}

// ---------------- pooling (segmented, no atomics) --------------------------
__global__ void k_pool2(const float* __restrict__ h, const int* __restrict__ gptr,
                        float* __restrict__ feats) {
    int g = blockIdx.x;
    int f4 = threadIdx.x;                  // 0..159, use first 150
    if (f4 >= 150) return;
    int start = gptr[g], end = gptr[g + 1];
    const float4* hv = (const float4*)h;
    float4 acc = make_float4(0.f, 0.f, 0.f, 0.f);
    for (int n = start; n < end; n++) {
        float4 v = hv[n * 150 + f4];
        acc.x += v.x; acc.y += v.y; acc.z += v.z; acc.w += v.w;
    }
    ((float4*)feats)[g * 150 + f4] = acc;
}

// ---------------- FFMA SGEMM (small GEMMs: K=9 layer0, classifier) ---------
#define BM 128
#define BN 128
#define BK 8

__global__ __launch_bounds__(256)
void k_sgemm(int M, int N, int K,
             const float* __restrict__ A, const float* __restrict__ B,
             const float* __restrict__ bias, float* __restrict__ C, int relu) {
    __shared__ float As[BK][BM + 4];
    __shared__ float Bs[BK][BN];

    int tid = threadIdx.x;
    int tx = tid & 15;
    int ty = tid >> 4;
    int m0 = blockIdx.y * BM;
    int n0 = blockIdx.x * BN;

    float acc[8][8];
#pragma unroll
    for (int i = 0; i < 8; i++)
#pragma unroll
        for (int j = 0; j < 8; j++) acc[i][j] = 0.f;

    for (int k0 = 0; k0 < K; k0 += BK) {
#pragma unroll
        for (int i = 0; i < 4; i++) {
            int e = tid * 4 + i;
            int m = e >> 3, k = e & 7;
            int gm = m0 + m, gk = k0 + k;
            As[k][m] = (gm < M && gk < K) ? A[gm * K + gk] : 0.f;
        }
#pragma unroll
        for (int i = 0; i < 4; i++) {
            int e = tid * 4 + i;
            int k = e >> 7, n = e & 127;
            int gn = n0 + n, gk = k0 + k;
            Bs[k][n] = (gn < N && gk < K) ? B[gk * N + gn] : 0.f;
        }
        __syncthreads();

#pragma unroll
        for (int k = 0; k < BK; k++) {
            float4 a0 = *(const float4*)&As[k][ty * 4];
            float4 a1 = *(const float4*)&As[k][64 + ty * 4];
            float4 b0 = *(const float4*)&Bs[k][tx * 4];
            float4 b1 = *(const float4*)&Bs[k][64 + tx * 4];
            float a[8] = {a0.x, a0.y, a0.z, a0.w, a1.x, a1.y, a1.z, a1.w};
            float b[8] = {b0.x, b0.y, b0.z, b0.w, b1.x, b1.y, b1.z, b1.w};
#pragma unroll
            for (int i = 0; i < 8; i++)
#pragma unroll
                for (int j = 0; j < 8; j++)
                    acc[i][j] = fmaf(a[i], b[j], acc[i][j]);
        }
        __syncthreads();
    }

#pragma unroll
    for (int i = 0; i < 8; i++) {
        int r = (i < 4) ? (ty * 4 + i) : (64 + ty * 4 + (i - 4));
        int gm = m0 + r;
        if (gm >= M) continue;
#pragma unroll
        for (int j = 0; j < 8; j++) {
            int c = (j < 4) ? (tx * 4 + j) : (64 + tx * 4 + (j - 4));
            int gn = n0 + c;
            if (gn >= N) continue;
            float v = acc[i][j] + bias[gn];
            if (relu) v = fmaxf(v, 0.f);
            C[gm * N + gn] = v;
        }
    }
}

// ---------------- 3xFP16 mma.sync GEMM, pair-packed hi/lo smem -------------
// C = act(A[M,K] @ B[K,N] + bias), fp32 in/out. 3-pass fp16 hi/lo split.
// smem: per buffer 4 regions (Ahi, Alo, Bhi, Blo), each [8][136] half2 words:
// word (kp, x) = half2( val(k=2kp, x), val(k=2kp+1, x) ) -> fragment regs are
// direct conflict-free LDS (bank = 8*lr + lq), zero PRMT in the mainloop.
#define GBM 128
#define GBN 128
#define GBK 16
#define PST 136                        // padded stride (words), 136%32=8
#define REGW (8 * PST)                 // 1088 words per region
#define BUFW (4 * REGW)                // 4352 words per buffer
#define OA_HI 0
#define OA_LO REGW
#define OB_HI (2 * REGW)
#define OB_LO (3 * REGW)

// fp16 conversions via PTX (avoids cuda_fp16.h)
__device__ __forceinline__ void pack_pair(float v0, float v1,
                                          uint32_t& wh, uint32_t& wl) {
    unsigned short h0, h1, l0, l1;
    float b0, b1;
    asm("cvt.rn.f16.f32 %0, %1;" : "=h"(h0) : "f"(v0));
    asm("cvt.rn.f16.f32 %0, %1;" : "=h"(h1) : "f"(v1));
    asm("cvt.f32.f16 %0, %1;" : "=f"(b0) : "h"(h0));
    asm("cvt.f32.f16 %0, %1;" : "=f"(b1) : "h"(h1));
    float r0 = v0 - b0, r1 = v1 - b1;
    asm("cvt.rn.f16.f32 %0, %1;" : "=h"(l0) : "f"(r0));
    asm("cvt.rn.f16.f32 %0, %1;" : "=h"(l1) : "f"(r1));
    wh = (uint32_t)h0 | ((uint32_t)h1 << 16);
    wl = (uint32_t)l0 | ((uint32_t)l1 << 16);
}

__device__ __forceinline__ void mma_f16(float* d, const uint32_t* a,
                                        uint32_t b0, uint32_t b1) {
    asm volatile(
        "mma.sync.aligned.m16n8k16.row.col.f32.f16.f16.f32 "
        "{%0,%1,%2,%3}, {%4,%5,%6,%7}, {%8,%9}, {%0,%1,%2,%3};\n"
        : "+f"(d[0]), "+f"(d[1]), "+f"(d[2]), "+f"(d[3])
        : "r"(a[0]), "r"(a[1]), "r"(a[2]), "r"(a[3]), "r"(b0), "r"(b1));
}

__global__ __launch_bounds__(256, 1)
void k_gemm_f16(int M, int N, int K,
                const float* __restrict__ A, const float* __restrict__ B,
                const float* __restrict__ bias, float* __restrict__ C, int relu) {
    __shared__ uint32_t sh[2][BUFW];

    int tid = threadIdx.x;
    int lane = tid & 31;
    int warp = tid >> 5;
    int wm = (warp >> 1) * 32;   // warp row offset in tile
    int wn = (warp & 1) * 64;    // warp col offset in tile
    int lq = lane >> 2;          // 0..7
    int lr = lane & 3;           // 0..3

    int m0 = blockIdx.y * GBM;
    int n0 = blockIdx.x * GBN;

    // A loader: thread covers row am, k ak..ak+7 (4 pair-words)
    int am = tid >> 1;            // 0..127
    int ak = (tid & 1) * 8;       // 0 or 8
    int akp = (tid & 1) * 4;      // pair-row base 0 or 4
    int gmA = m0 + am;
    bool a_ok = (gmA < M);
    // B loader: thread covers k rows 2kb,2kb+1, n nb..nb+3 (4 pair-words)
    int kb = tid >> 5;            // 0..7
    int nb = (tid & 31) * 4;      // 0..124

    float acc[2][8][4];
#pragma unroll
    for (int i = 0; i < 2; i++)
#pragma unroll
        for (int j = 0; j < 8; j++)
#pragma unroll
            for (int c = 0; c < 4; c++) acc[i][j][c] = 0.f;

    float ra[8], ru[4], rv[4];
    int NIT = (K + GBK - 1) / GBK;

    // ---- prologue: load tile 0 ----
    {
        if (a_ok && (ak + 8 <= K)) {
            const float* p = &A[gmA * K + ak];
            float4 v0 = *(const float4*)p;
            float4 v1 = *(const float4*)(p + 4);
            ra[0] = v0.x; ra[1] = v0.y; ra[2] = v0.z; ra[3] = v0.w;
            ra[4] = v1.x; ra[5] = v1.y; ra[6] = v1.z; ra[7] = v1.w;
        } else {
#pragma unroll
            for (int i = 0; i < 8; i++) {
                int gk = ak + i;
                ra[i] = (a_ok && gk < K) ? A[gmA * K + gk] : 0.f;
            }
        }
        int gk0 = 2 * kb, gk1 = 2 * kb + 1;
        int gn = n0 + nb;
        if (gk1 < K && gn + 4 <= N) {
            float4 u = *(const float4*)&B[gk0 * N + gn];
            float4 v = *(const float4*)&B[gk1 * N + gn];
            ru[0] = u.x; ru[1] = u.y; ru[2] = u.z; ru[3] = u.w;
            rv[0] = v.x; rv[1] = v.y; rv[2] = v.z; rv[3] = v.w;
        } else {
#pragma unroll
            for (int j = 0; j < 4; j++) {
                int n = gn + j;
                ru[j] = (gk0 < K && n < N) ? B[gk0 * N + n] : 0.f;
                rv[j] = (gk1 < K && n < N) ? B[gk1 * N + n] : 0.f;
            }
        }
        // STS
        uint32_t* buf = sh[0];
#pragma unroll
        for (int i = 0; i < 4; i++) {
            uint32_t wh, wl;
            pack_pair(ra[2 * i], ra[2 * i + 1], wh, wl);
            buf[OA_HI + (akp + i) * PST + am] = wh;
            buf[OA_LO + (akp + i) * PST + am] = wl;
        }
        uint32_t bh[4], bl[4];
#pragma unroll
        for (int j = 0; j < 4; j++) pack_pair(ru[j], rv[j], bh[j], bl[j]);
        *(uint4*)&buf[OB_HI + kb * PST + nb] = make_uint4(bh[0], bh[1], bh[2], bh[3]);
        *(uint4*)&buf[OB_LO + kb * PST + nb] = make_uint4(bl[0], bl[1], bl[2], bl[3]);
    }
    __syncthreads();

    int buf_i = 0;
    for (int it = 0; it < NIT; it++) {
        bool has_next = (it + 1 < NIT);
        // ---- prefetch next tile into registers ----
        if (has_next) {
            int k0 = (it + 1) * GBK;
            if (a_ok && (k0 + ak + 8 <= K)) {
                const float* p = &A[gmA * K + k0 + ak];
                float4 v0 = *(const float4*)p;
                float4 v1 = *(const float4*)(p + 4);
                ra[0] = v0.x; ra[1] = v0.y; ra[2] = v0.z; ra[3] = v0.w;
                ra[4] = v1.x; ra[5] = v1.y; ra[6] = v1.z; ra[7] = v1.w;
            } else {
#pragma unroll
                for (int i = 0; i < 8; i++) {
                    int gk = k0 + ak + i;
                    ra[i] = (a_ok && gk < K) ? A[gmA * K + gk] : 0.f;
                }
            }
            int gk0 = k0 + 2 * kb, gk1 = gk0 + 1;
            int gn = n0 + nb;
            if (gk1 < K && gn + 4 <= N) {
                float4 u = *(const float4*)&B[gk0 * N + gn];
                float4 v = *(const float4*)&B[gk1 * N + gn];
                ru[0] = u.x; ru[1] = u.y; ru[2] = u.z; ru[3] = u.w;
                rv[0] = v.x; rv[1] = v.y; rv[2] = v.z; rv[3] = v.w;
            } else {
#pragma unroll
                for (int j = 0; j < 4; j++) {
                    int n = gn + j;
                    ru[j] = (gk0 < K && n < N) ? B[gk0 * N + n] : 0.f;
                    rv[j] = (gk1 < K && n < N) ? B[gk1 * N + n] : 0.f;
                }
            }
        }

        // ---- compute on current buffer: direct fragment LDS, no PRMT ----
        const uint32_t* bufc = sh[buf_i];
        uint32_t ah[2][4], al[2][4];
#pragma unroll
        for (int i = 0; i < 2; i++) {
            int r1 = wm + i * 16 + lq;
            ah[i][0] = bufc[OA_HI + lr * PST + r1];
            ah[i][1] = bufc[OA_HI + lr * PST + r1 + 8];
            ah[i][2] = bufc[OA_HI + (lr + 4) * PST + r1];
            ah[i][3] = bufc[OA_HI + (lr + 4) * PST + r1 + 8];
            al[i][0] = bufc[OA_LO + lr * PST + r1];
            al[i][1] = bufc[OA_LO + lr * PST + r1 + 8];
            al[i][2] = bufc[OA_LO + (lr + 4) * PST + r1];
            al[i][3] = bufc[OA_LO + (lr + 4) * PST + r1 + 8];
        }
#pragma unroll
        for (int j = 0; j < 8; j++) {
            int n = wn + j * 8 + lq;
            uint32_t bh0 = bufc[OB_HI + lr * PST + n];
            uint32_t bh1 = bufc[OB_HI + (lr + 4) * PST + n];
            uint32_t bl0 = bufc[OB_LO + lr * PST + n];
            uint32_t bl1 = bufc[OB_LO + (lr + 4) * PST + n];
#pragma unroll
            for (int i = 0; i < 2; i++) {
                mma_f16(acc[i][j], ah[i], bh0, bh1);
                mma_f16(acc[i][j], ah[i], bl0, bl1);
                mma_f16(acc[i][j], al[i], bh0, bh1);
            }
        }

        // ---- convert + STS next tile into other buffer ----
        if (has_next) {
            uint32_t* bufn = sh[buf_i ^ 1];
#pragma unroll
            for (int i = 0; i < 4; i++) {
                uint32_t wh, wl;
                pack_pair(ra[2 * i], ra[2 * i + 1], wh, wl);
                bufn[OA_HI + (akp + i) * PST + am] = wh;
                bufn[OA_LO + (akp + i) * PST + am] = wl;
            }
            uint32_t bh[4], bl[4];
#pragma unroll
            for (int j = 0; j < 4; j++) pack_pair(ru[j], rv[j], bh[j], bl[j]);
            *(uint4*)&bufn[OB_HI + kb * PST + nb] = make_uint4(bh[0], bh[1], bh[2], bh[3]);
            *(uint4*)&bufn[OB_LO + kb * PST + nb] = make_uint4(bl[0], bl[1], bl[2], bl[3]);
        }
        __syncthreads();
        buf_i ^= 1;
    }

    // ---- epilogue: bias + optional relu ----
    int lr2 = 2 * lr;
#pragma unroll
    for (int i = 0; i < 2; i++) {
#pragma unroll
        for (int c = 0; c < 4; c++) {
            int row = m0 + wm + i * 16 + lq + ((c >= 2) ? 8 : 0);
            if (row >= M) continue;
#pragma unroll
            for (int j = 0; j < 8; j++) {
                int col = n0 + wn + j * 8 + lr2 + (c & 1);
                if (col >= N) continue;
                float v = acc[i][j][c] + bias[col];
                if (relu) v = fmaxf(v, 0.f);
                C[row * N + col] = v;
            }
        }
    }
}

// ---------------- host orchestration ---------------------------------------
static inline void sgemm(int M, int N, int K, const float* A, const float* B,
                         const float* bias, float* C, int relu) {
    dim3 grid((N + BN - 1) / BN, (M + BM - 1) / BM);
    k_sgemm<<<grid, 256>>>(M, N, K, A, B, bias, C, relu);
}

static inline void gemm_f16(int M, int N, int K, const float* A, const float* B,
                            const float* bias, float* C, int relu) {
    dim3 grid((N + GBN - 1) / GBN, (M + GBM - 1) / GBM);
    k_gemm_f16<<<grid, 256>>>(M, N, K, A, B, bias, C, relu);
}

extern "C" void kernel_launch(void* const* d_in, const int* in_sizes, int n_in,
                              void* d_out, int out_size) {
    const float* x      = (const float*)d_in[0];
    const void*  edges  = d_in[1];
    const void*  batch  = d_in[2];
    const float* w1_0 = (const float*)d_in[3];
    const float* b1_0 = (const float*)d_in[4];
    const float* w2_0 = (const float*)d_in[5];
    const float* b2_0 = (const float*)d_in[6];
    const float* w1_r = (const float*)d_in[7];
    const float* b1_r = (const float*)d_in[8];
    const float* w2_r = (const float*)d_in[9];
    const float* b2_r = (const float*)d_in[10];
    const float* cw1  = (const float*)d_in[11];
    const float* cb1  = (const float*)d_in[12];
    const float* cw2  = (const float*)d_in[13];
    const float* cb2  = (const float*)d_in[14];
    const float* cw3  = (const float*)d_in[15];
    const float* cb3  = (const float*)d_in[16];
    float* out = (float*)d_out;

    float *h, *agg, *t1, *feats, *z1, *z2;
    int *src, *dst, *bat, *deg, *rowptr, *cursor, *col, *gptr;
    cudaGetSymbolAddress((void**)&h, g_h);
    cudaGetSymbolAddress((void**)&agg, g_agg);
    cudaGetSymbolAddress((void**)&t1, g_t1);
    cudaGetSymbolAddress((void**)&feats, g_feats);
    cudaGetSymbolAddress((void**)&z1, g_z1);
    cudaGetSymbolAddress((void**)&z2, g_z2);
    cudaGetSymbolAddress((void**)&src, g_src);
    cudaGetSymbolAddress((void**)&dst, g_dst);
    cudaGetSymbolAddress((void**)&bat, g_batch);
    cudaGetSymbolAddress((void**)&deg, g_deg);
    cudaGetSymbolAddress((void**)&rowptr, g_rowptr);
    cudaGetSymbolAddress((void**)&cursor, g_cursor);
    cudaGetSymbolAddress((void**)&col, g_col);
    cudaGetSymbolAddress((void**)&gptr, g_gptr);

    // 1) index dtype detect + convert
    k_detect<<<1, 32>>>((const unsigned long long*)edges);
    {
        int n = (EE > NN) ? EE : NN;
        k_convert<<<(n + 255) / 256, 256>>>(edges, batch);
    }

    // 2) CSR build (dst-major, col = src) + graph ranges
    k_zero_int<<<(NN + 255) / 256, 256>>>(deg, NN);
    k_count<<<(EE + 255) / 256, 256>>>(dst, deg);
    k_scan<<<1, 1024>>>(deg, rowptr, NN);
    k_copy_int<<<(NN + 255) / 256, 256>>>(rowptr, cursor, NN);
    k_fill<<<(EE + 255) / 256, 256>>>(src, dst, cursor, col);
    k_gptr<<<(NG + 1 + 255) / 256, 256>>>(bat, gptr);

    // 3) layer 0 (input width 9) — FFMA path for K=9
    k_aggregate<<<NN, 32>>>(x, agg, rowptr, col, INF);
    sgemm(NN, HID, INF, agg, w1_0, b1_0, t1, 1);
    gemm_f16(NN, HID, HID, t1, w2_0, b2_0, h, 1);  // fused inter-layer relu

    // 4) layers 1..4 — tensor-core GEMMs
    for (int i = 0; i < 4; i++) {
        k_aggregate_v4<<<NN, 160>>>(h, agg, rowptr, col);
        gemm_f16(NN, HID, HID, agg, w1_r + i * HID * HID, b1_r + i * HID, t1, 1);
        gemm_f16(NN, HID, HID, t1, w2_r + i * HID * HID, b2_r + i * HID, h, (i < 3) ? 1 : 0);
    }

    // 5) global_add_pool (segmented, batch_ind sorted)
    k_pool2<<<NG, 160>>>(h, gptr, feats);

    // 6) classifier MLP (small — FFMA path)
    sgemm(NG, CHID, HID, feats, cw1, cb1, z1, 1);
    sgemm(NG, CHID, CHID, z1, cw2, cb2, z2, 1);
    sgemm(NG, NT, CHID, z2, cw3, cb3, out, 0);
}

// round 12
// speedup vs baseline: 2.5941x; 1.2436x over previous
#include <cuda_runtime.h>
#include <cstdint>

// Problem constants (match reference)
#define NN   30000
#define EE   300000
#define NG   512
#define HID  600
#define INF  9
#define NT   128
#define CHID 256

// ---------------- device scratch (allocation-free rule: device globals) ----
__device__ float g_h[NN * HID];
__device__ float g_agg[NN * HID];
__device__ float g_t1[NN * HID];
__device__ float g_feats[NG * HID];
__device__ float g_z1[NG * CHID];
__device__ float g_z2[NG * CHID];

__device__ int g_src[EE];
__device__ int g_dst[EE];
__device__ int g_batch[NN];
__device__ int g_deg[NN];
__device__ int g_rowptr[NN + 1];
__device__ int g_cursor[NN];
__device__ int g_col[EE];
__device__ int g_gptr[NG + 1];
__device__ int g_is64;

// ---------------- index dtype detection + conversion ----------------------
__global__ void k_detect(const unsigned long long* __restrict__ p) {
    if (threadIdx.x == 0 && blockIdx.x == 0) {
        int is64 = 1;
        for (int i = 0; i < 256; i++)
            if (p[i] >> 32) { is64 = 0; break; }
        g_is64 = is64;
    }
}

__global__ void k_convert(const void* __restrict__ edges,
                          const void* __restrict__ batch) {
    int i = blockIdx.x * blockDim.x + threadIdx.x;
    int is64 = g_is64;
    if (i < EE) {
        if (is64) {
            const long long* p = (const long long*)edges;
            g_src[i] = (int)p[i];
            g_dst[i] = (int)p[EE + i];
        } else {
            const int* p = (const int*)edges;
            g_src[i] = p[i];
            g_dst[i] = p[EE + i];
        }
    }
    if (i < NN) {
        if (is64) {
            const long long* p = (const long long*)batch;
            g_batch[i] = (int)p[i];
        } else {
            const int* p = (const int*)batch;
            g_batch[i] = p[i];
        }
    }
}

// ---------------- small utility kernels ------------------------------------
__global__ void k_zero_int(int* p, int n) {
    int i = blockIdx.x * blockDim.x + threadIdx.x;
    if (i < n) p[i] = 0;
}
__global__ void k_copy_int(const int* __restrict__ a, int* __restrict__ b, int n) {
    int i = blockIdx.x * blockDim.x + threadIdx.x;
    if (i < n) b[i] = a[i];
}

// ---------------- CSR build (dst-major) ------------------------------------
__global__ void k_count(const int* __restrict__ dst, int* __restrict__ deg) {
    int i = blockIdx.x * blockDim.x + threadIdx.x;
    if (i < EE) atomicAdd(&deg[dst[i]], 1);
}

__global__ void k_scan(const int* __restrict__ in, int* __restrict__ out, int n) {
    __shared__ int s[1024];
    __shared__ int s_carry;
    int tid = threadIdx.x;
    if (tid == 0) s_carry = 0;
    __syncthreads();
    for (int base = 0; base < n; base += 1024) {
        int i = base + tid;
        int v = (i < n) ? in[i] : 0;
        s[tid] = v;
        __syncthreads();
        for (int off = 1; off < 1024; off <<= 1) {
            int t = (tid >= off) ? s[tid - off] : 0;
            __syncthreads();
            s[tid] += t;
            __syncthreads();
        }
        int c = s_carry;
        if (i < n) out[i] = c + s[tid] - v;
        __syncthreads();
        if (tid == 0) s_carry = c + s[1023];
        __syncthreads();
    }
    if (tid == 0) out[n] = s_carry;
}

__global__ void k_fill(const int* __restrict__ src, const int* __restrict__ dst,
                       int* __restrict__ cursor, int* __restrict__ col) {
    int i = blockIdx.x * blockDim.x + threadIdx.x;
    if (i < EE) {
        int p = atomicAdd(&cursor[dst[i]], 1);
        col[p] = src[i];
    }
}

// ---------------- graph ranges (batch_ind is sorted) -----------------------
__global__ void k_gptr(const int* __restrict__ batch, int* __restrict__ gptr) {
    int g = blockIdx.x * blockDim.x + threadIdx.x;
    if (g > NG) return;
    int lo = 0, hi = NN;
    while (lo < hi) {
        int mid = (lo + hi) >> 1;
        if (batch[mid] < g) lo = mid + 1; else hi = mid;
    }
    gptr[g] = lo;
}

// ---------------- aggregation --------------------------------------------
__global__ void k_aggregate(const float* __restrict__ h, float* __restrict__ agg,
                            const int* __restrict__ rowptr,
                            const int* __restrict__ col, int width) {
    __shared__ int s_nbr[64];
    int node = blockIdx.x;
    int f = threadIdx.x;
    int CH = (blockDim.x < 64) ? blockDim.x : 64;
    int start = rowptr[node], end = rowptr[node + 1];
    float acc = (f < width) ? h[node * width + f] : 0.f;
    for (int base = start; base < end; base += CH) {
        int cnt = end - base;
        if (cnt > CH) cnt = CH;
        if ((int)threadIdx.x < cnt) s_nbr[threadIdx.x] = col[base + threadIdx.x];
        __syncthreads();
        if (f < width) {
            for (int j = 0; j < cnt; j++)
                acc += h[s_nbr[j] * width + f];
        }
        __syncthreads();
    }
    if (f < width) agg[node * width + f] = acc;
}

__global__ void k_aggregate_v4(const float* __restrict__ h, float* __restrict__ agg,
                               const int* __restrict__ rowptr,
                               const int* __restrict__ col) {
    __shared__ int s_nbr[32];
    int node = blockIdx.x;
    int f4 = threadIdx.x;                  // 0..159, use first 150
    int start = rowptr[node], end = rowptr[node + 1];
    const float4* hv = (const float4*)h;
    float4 acc;
    if (f4 < 150) acc = hv[node * 150 + f4];
    else acc = make_float4(0.f, 0.f, 0.f, 0.f);
    for (int base = start; base < end; base += 32) {
        int cnt = end - base;
        if (cnt > 32) cnt = 32;
        if ((int)threadIdx.x < cnt) s_nbr[threadIdx.x] = col[base + threadIdx.x];
        __syncthreads();
        if (f4 < 150) {
            for (int j = 0; j < cnt; j++) {
                float4 v = hv[s_nbr[j] * 150 + f4];
                acc.x += v.x; acc.y += v.y; acc.z += v.z; acc.w += v.w;
            }
        }
        __syncthreads();
    }
    if (f4 < 150) ((float4*)agg)[node * 150 + f4] = acc;
}

// ---------------- pooling (segmented, no atomics) --------------------------
__global__ void k_pool2(const float* __restrict__ h, const int* __restrict__ gptr,
                        float* __restrict__ feats) {
    int g = blockIdx.x;
    int f4 = threadIdx.x;                  // 0..159, use first 150
    if (f4 >= 150) return;
    int start = gptr[g], end = gptr[g + 1];
    const float4* hv = (const float4*)h;
    float4 acc = make_float4(0.f, 0.f, 0.f, 0.f);
    for (int n = start; n < end; n++) {
        float4 v = hv[n * 150 + f4];
        acc.x += v.x; acc.y += v.y; acc.z += v.z; acc.w += v.w;
    }
    ((float4*)feats)[g * 150 + f4] = acc;
}

// ---------------- FFMA SGEMM (small GEMMs: K=9 layer0, classifier) ---------
#define BM 128
#define BN 128
#define BK 8

__global__ __launch_bounds__(256)
void k_sgemm(int M, int N, int K,
             const float* __restrict__ A, const float* __restrict__ B,
             const float* __restrict__ bias, float* __restrict__ C, int relu) {
    __shared__ float As[BK][BM + 4];
    __shared__ float Bs[BK][BN];

    int tid = threadIdx.x;
    int tx = tid & 15;
    int ty = tid >> 4;
    int m0 = blockIdx.y * BM;
    int n0 = blockIdx.x * BN;

    float acc[8][8];
#pragma unroll
    for (int i = 0; i < 8; i++)
#pragma unroll
        for (int j = 0; j < 8; j++) acc[i][j] = 0.f;

    for (int k0 = 0; k0 < K; k0 += BK) {
#pragma unroll
        for (int i = 0; i < 4; i++) {
            int e = tid * 4 + i;
            int m = e >> 3, k = e & 7;
            int gm = m0 + m, gk = k0 + k;
            As[k][m] = (gm < M && gk < K) ? A[gm * K + gk] : 0.f;
        }
#pragma unroll
        for (int i = 0; i < 4; i++) {
            int e = tid * 4 + i;
            int k = e >> 7, n = e & 127;
            int gn = n0 + n, gk = k0 + k;
            Bs[k][n] = (gn < N && gk < K) ? B[gk * N + gn] : 0.f;
        }
        __syncthreads();

#pragma unroll
        for (int k = 0; k < BK; k++) {
            float4 a0 = *(const float4*)&As[k][ty * 4];
            float4 a1 = *(const float4*)&As[k][64 + ty * 4];
            float4 b0 = *(const float4*)&Bs[k][tx * 4];
            float4 b1 = *(const float4*)&Bs[k][64 + tx * 4];
            float a[8] = {a0.x, a0.y, a0.z, a0.w, a1.x, a1.y, a1.z, a1.w};
            float b[8] = {b0.x, b0.y, b0.z, b0.w, b1.x, b1.y, b1.z, b1.w};
#pragma unroll
            for (int i = 0; i < 8; i++)
#pragma unroll
                for (int j = 0; j < 8; j++)
                    acc[i][j] = fmaf(a[i], b[j], acc[i][j]);
        }
        __syncthreads();
    }

#pragma unroll
    for (int i = 0; i < 8; i++) {
        int r = (i < 4) ? (ty * 4 + i) : (64 + ty * 4 + (i - 4));
        int gm = m0 + r;
        if (gm >= M) continue;
#pragma unroll
        for (int j = 0; j < 8; j++) {
            int c = (j < 4) ? (tx * 4 + j) : (64 + tx * 4 + (j - 4));
            int gn = n0 + c;
            if (gn >= N) continue;
            float v = acc[i][j] + bias[gn];
            if (relu) v = fmaxf(v, 0.f);
            C[gm * N + gn] = v;
        }
    }
}

// ---------------- 3xFP16 mma.sync GEMM, pair-packed hi/lo smem -------------
// C = act(A[M,K] @ B[K,N] + bias), fp32 in/out. 3-pass fp16 hi/lo split.
// smem: per buffer 4 regions (Ahi, Alo, Bhi, Blo), each [8][136] half2 words;
// fragment regs are direct conflict-free LDS (bank = 8*lr + lq), zero PRMT.
// __launch_bounds__(256,2): 2 CTAs/SM (4 warps/SMSP) for latency hiding.
#define GBM 128
#define GBN 128
#define GBK 16
#define PST 136                        // padded stride (words), 136%32=8
#define REGW (8 * PST)                 // 1088 words per region
#define BUFW (4 * REGW)                // 4352 words per buffer
#define OA_HI 0
#define OA_LO REGW
#define OB_HI (2 * REGW)
#define OB_LO (3 * REGW)

// fp16 conversions via PTX (avoids cuda_fp16.h)
__device__ __forceinline__ void pack_pair(float v0, float v1,
                                          uint32_t& wh, uint32_t& wl) {
    unsigned short h0, h1, l0, l1;
    float b0, b1;
    asm("cvt.rn.f16.f32 %0, %1;" : "=h"(h0) : "f"(v0));
    asm("cvt.rn.f16.f32 %0, %1;" : "=h"(h1) : "f"(v1));
    asm("cvt.f32.f16 %0, %1;" : "=f"(b0) : "h"(h0));
    asm("cvt.f32.f16 %0, %1;" : "=f"(b1) : "h"(h1));
    float r0 = v0 - b0, r1 = v1 - b1;
    asm("cvt.rn.f16.f32 %0, %1;" : "=h"(l0) : "f"(r0));
    asm("cvt.rn.f16.f32 %0, %1;" : "=h"(l1) : "f"(r1));
    wh = (uint32_t)h0 | ((uint32_t)h1 << 16);
    wl = (uint32_t)l0 | ((uint32_t)l1 << 16);
}

__device__ __forceinline__ void mma_f16(float* d, const uint32_t* a,
                                        uint32_t b0, uint32_t b1) {
    asm volatile(
        "mma.sync.aligned.m16n8k16.row.col.f32.f16.f16.f32 "
        "{%0,%1,%2,%3}, {%4,%5,%6,%7}, {%8,%9}, {%0,%1,%2,%3};\n"
        : "+f"(d[0]), "+f"(d[1]), "+f"(d[2]), "+f"(d[3])
        : "r"(a[0]), "r"(a[1]), "r"(a[2]), "r"(a[3]), "r"(b0), "r"(b1));
}

__global__ __launch_bounds__(256, 2)
void k_gemm_f16(int M, int N, int K,
                const float* __restrict__ A, const float* __restrict__ B,
                const float* __restrict__ bias, float* __restrict__ C, int relu) {
    __shared__ uint32_t sh[2][BUFW];

    int tid = threadIdx.x;
    int lane = tid & 31;
    int warp = tid >> 5;
    int wm = (warp >> 1) * 32;   // warp row offset in tile
    int wn = (warp & 1) * 64;    // warp col offset in tile
    int lq = lane >> 2;          // 0..7
    int lr = lane & 3;           // 0..3

    int m0 = blockIdx.y * GBM;
    int n0 = blockIdx.x * GBN;

    // A loader: thread covers row am, k ak..ak+7 (4 pair-words)
    int am = tid >> 1;            // 0..127
    int ak = (tid & 1) * 8;       // 0 or 8
    int akp = (tid & 1) * 4;      // pair-row base 0 or 4
    int gmA = m0 + am;
    bool a_ok = (gmA < M);
    // B loader: thread covers k rows 2kb,2kb+1, n nb..nb+3 (4 pair-words)
    int kb = tid >> 5;            // 0..7
    int nb = (tid & 31) * 4;      // 0..124

    float acc[2][8][4];
#pragma unroll
    for (int i = 0; i < 2; i++)
#pragma unroll
        for (int j = 0; j < 8; j++)
#pragma unroll
            for (int c = 0; c < 4; c++) acc[i][j][c] = 0.f;

    float ra[8], ru[4], rv[4];
    int NIT = (K + GBK - 1) / GBK;

    // ---- prologue: load tile 0 ----
    {
        if (a_ok && (ak + 8 <= K)) {
            const float* p = &A[gmA * K + ak];
            float4 v0 = *(const float4*)p;
            float4 v1 = *(const float4*)(p + 4);
            ra[0] = v0.x; ra[1] = v0.y; ra[2] = v0.z; ra[3] = v0.w;
            ra[4] = v1.x; ra[5] = v1.y; ra[6] = v1.z; ra[7] = v1.w;
        } else {
#pragma unroll
            for (int i = 0; i < 8; i++) {
                int gk = ak + i;
                ra[i] = (a_ok && gk < K) ? A[gmA * K + gk] : 0.f;
            }
        }
        int gk0 = 2 * kb, gk1 = 2 * kb + 1;
        int gn = n0 + nb;
        if (gk1 < K && gn + 4 <= N) {
            float4 u = *(const float4*)&B[gk0 * N + gn];
            float4 v = *(const float4*)&B[gk1 * N + gn];
            ru[0] = u.x; ru[1] = u.y; ru[2] = u.z; ru[3] = u.w;
            rv[0] = v.x; rv[1] = v.y; rv[2] = v.z; rv[3] = v.w;
        } else {
#pragma unroll
            for (int j = 0; j < 4; j++) {
                int n = gn + j;
                ru[j] = (gk0 < K && n < N) ? B[gk0 * N + n] : 0.f;
                rv[j] = (gk1 < K && n < N) ? B[gk1 * N + n] : 0.f;
            }
        }
        uint32_t* buf = sh[0];
#pragma unroll
        for (int i = 0; i < 4; i++) {
            uint32_t wh, wl;
            pack_pair(ra[2 * i], ra[2 * i + 1], wh, wl);
            buf[OA_HI + (akp + i) * PST + am] = wh;
            buf[OA_LO + (akp + i) * PST + am] = wl;
        }
        uint32_t bh[4], bl[4];
#pragma unroll
        for (int j = 0; j < 4; j++) pack_pair(ru[j], rv[j], bh[j], bl[j]);
        *(uint4*)&buf[OB_HI + kb * PST + nb] = make_uint4(bh[0], bh[1], bh[2], bh[3]);
        *(uint4*)&buf[OB_LO + kb * PST + nb] = make_uint4(bl[0], bl[1], bl[2], bl[3]);
    }
    __syncthreads();

    int buf_i = 0;
    for (int it = 0; it < NIT; it++) {
        bool has_next = (it + 1 < NIT);
        // ---- prefetch next tile into registers ----
        if (has_next) {
            int k0 = (it + 1) * GBK;
            if (a_ok && (k0 + ak + 8 <= K)) {
                const float* p = &A[gmA * K + k0 + ak];
                float4 v0 = *(const float4*)p;
                float4 v1 = *(const float4*)(p + 4);
                ra[0] = v0.x; ra[1] = v0.y; ra[2] = v0.z; ra[3] = v0.w;
                ra[4] = v1.x; ra[5] = v1.y; ra[6] = v1.z; ra[7] = v1.w;
            } else {
#pragma unroll
                for (int i = 0; i < 8; i++) {
                    int gk = k0 + ak + i;
                    ra[i] = (a_ok && gk < K) ? A[gmA * K + gk] : 0.f;
                }
            }
            int gk0 = k0 + 2 * kb, gk1 = gk0 + 1;
            int gn = n0 + nb;
            if (gk1 < K && gn + 4 <= N) {
                float4 u = *(const float4*)&B[gk0 * N + gn];
                float4 v = *(const float4*)&B[gk1 * N + gn];
                ru[0] = u.x; ru[1] = u.y; ru[2] = u.z; ru[3] = u.w;
                rv[0] = v.x; rv[1] = v.y; rv[2] = v.z; rv[3] = v.w;
            } else {
#pragma unroll
                for (int j = 0; j < 4; j++) {
                    int n = gn + j;
                    ru[j] = (gk0 < K && n < N) ? B[gk0 * N + n] : 0.f;
                    rv[j] = (gk1 < K && n < N) ? B[gk1 * N + n] : 0.f;
                }
            }
        }

        // ---- compute on current buffer: direct fragment LDS ----
        const uint32_t* bufc = sh[buf_i];
        uint32_t ah[2][4], al[2][4];
#pragma unroll
        for (int i = 0; i < 2; i++) {
            int r1 = wm + i * 16 + lq;
            ah[i][0] = bufc[OA_HI + lr * PST + r1];
            ah[i][1] = bufc[OA_HI + lr * PST + r1 + 8];
            ah[i][2] = bufc[OA_HI + (lr + 4) * PST + r1];
            ah[i][3] = bufc[OA_HI + (lr + 4) * PST + r1 + 8];
            al[i][0] = bufc[OA_LO + lr * PST + r1];
            al[i][1] = bufc[OA_LO + lr * PST + r1 + 8];
            al[i][2] = bufc[OA_LO + (lr + 4) * PST + r1];
            al[i][3] = bufc[OA_LO + (lr + 4) * PST + r1 + 8];
        }
#pragma unroll
        for (int j = 0; j < 8; j++) {
            int n = wn + j * 8 + lq;
            uint32_t bh0 = bufc[OB_HI + lr * PST + n];
            uint32_t bh1 = bufc[OB_HI + (lr + 4) * PST + n];
            uint32_t bl0 = bufc[OB_LO + lr * PST + n];
            uint32_t bl1 = bufc[OB_LO + (lr + 4) * PST + n];
            // pass-interleaved: dependent MMAs on same acc are 2 apart
            mma_f16(acc[0][j], ah[0], bh0, bh1);
            mma_f16(acc[1][j], ah[1], bh0, bh1);
            mma_f16(acc[0][j], ah[0], bl0, bl1);
            mma_f16(acc[1][j], ah[1], bl0, bl1);
            mma_f16(acc[0][j], al[0], bh0, bh1);
            mma_f16(acc[1][j], al[1], bh0, bh1);
        }

        // ---- convert + STS next tile into other buffer ----
        if (has_next) {
            uint32_t* bufn = sh[buf_i ^ 1];
#pragma unroll
            for (int i = 0; i < 4; i++) {
                uint32_t wh, wl;
                pack_pair(ra[2 * i], ra[2 * i + 1], wh, wl);
                bufn[OA_HI + (akp + i) * PST + am] = wh;
                bufn[OA_LO + (akp + i) * PST + am] = wl;
            }
            uint32_t bh[4], bl[4];
#pragma unroll
            for (int j = 0; j < 4; j++) pack_pair(ru[j], rv[j], bh[j], bl[j]);
            *(uint4*)&bufn[OB_HI + kb * PST + nb] = make_uint4(bh[0], bh[1], bh[2], bh[3]);
            *(uint4*)&bufn[OB_LO + kb * PST + nb] = make_uint4(bl[0], bl[1], bl[2], bl[3]);
        }
        __syncthreads();
        buf_i ^= 1;
    }

    // ---- epilogue: bias + optional relu ----
    int lr2 = 2 * lr;
#pragma unroll
    for (int i = 0; i < 2; i++) {
#pragma unroll
        for (int c = 0; c < 4; c++) {
            int row = m0 + wm + i * 16 + lq + ((c >= 2) ? 8 : 0);
            if (row >= M) continue;
#pragma unroll
            for (int j = 0; j < 8; j++) {
                int col = n0 + wn + j * 8 + lr2 + (c & 1);
                if (col >= N) continue;
                float v = acc[i][j][c] + bias[col];
                if (relu) v = fmaxf(v, 0.f);
                C[row * N + col] = v;
            }
        }
    }
}

// ---------------- host orchestration ---------------------------------------
static inline void sgemm(int M, int N, int K, const float* A, const float* B,
                         const float* bias, float* C, int relu) {
    dim3 grid((N + BN - 1) / BN, (M + BM - 1) / BM);
    k_sgemm<<<grid, 256>>>(M, N, K, A, B, bias, C, relu);
}

static inline void gemm_f16(int M, int N, int K, const float* A, const float* B,
                            const float* bias, float* C, int relu) {
    dim3 grid((N + GBN - 1) / GBN, (M + GBM - 1) / GBM);
    k_gemm_f16<<<grid, 256>>>(M, N, K, A, B, bias, C, relu);
}

extern "C" void kernel_launch(void* const* d_in, const int* in_sizes, int n_in,
                              void* d_out, int out_size) {
    const float* x      = (const float*)d_in[0];
    const void*  edges  = d_in[1];
    const void*  batch  = d_in[2];
    const float* w1_0 = (const float*)d_in[3];
    const float* b1_0 = (const float*)d_in[4];
    const float* w2_0 = (const float*)d_in[5];
    const float* b2_0 = (const float*)d_in[6];
    const float* w1_r = (const float*)d_in[7];
    const float* b1_r = (const float*)d_in[8];
    const float* w2_r = (const float*)d_in[9];
    const float* b2_r = (const float*)d_in[10];
    const float* cw1  = (const float*)d_in[11];
    const float* cb1  = (const float*)d_in[12];
    const float* cw2  = (const float*)d_in[13];
    const float* cb2  = (const float*)d_in[14];
    const float* cw3  = (const float*)d_in[15];
    const float* cb3  = (const float*)d_in[16];
    float* out = (float*)d_out;

    float *h, *agg, *t1, *feats, *z1, *z2;
    int *src, *dst, *bat, *deg, *rowptr, *cursor, *col, *gptr;
    cudaGetSymbolAddress((void**)&h, g_h);
    cudaGetSymbolAddress((void**)&agg, g_agg);
    cudaGetSymbolAddress((void**)&t1, g_t1);
    cudaGetSymbolAddress((void**)&feats, g_feats);
    cudaGetSymbolAddress((void**)&z1, g_z1);
    cudaGetSymbolAddress((void**)&z2, g_z2);
    cudaGetSymbolAddress((void**)&src, g_src);
    cudaGetSymbolAddress((void**)&dst, g_dst);
    cudaGetSymbolAddress((void**)&bat, g_batch);
    cudaGetSymbolAddress((void**)&deg, g_deg);
    cudaGetSymbolAddress((void**)&rowptr, g_rowptr);
    cudaGetSymbolAddress((void**)&cursor, g_cursor);
    cudaGetSymbolAddress((void**)&col, g_col);
    cudaGetSymbolAddress((void**)&gptr, g_gptr);

    // 1) index dtype detect + convert
    k_detect<<<1, 32>>>((const unsigned long long*)edges);
    {
        int n = (EE > NN) ? EE : NN;
        k_convert<<<(n + 255) / 256, 256>>>(edges, batch);
    }

    // 2) CSR build (dst-major, col = src) + graph ranges
    k_zero_int<<<(NN + 255) / 256, 256>>>(deg, NN);
    k_count<<<(EE + 255) / 256, 256>>>(dst, deg);
    k_scan<<<1, 1024>>>(deg, rowptr, NN);
    k_copy_int<<<(NN + 255) / 256, 256>>>(rowptr, cursor, NN);
    k_fill<<<(EE + 255) / 256, 256>>>(src, dst, cursor, col);
    k_gptr<<<(NG + 1 + 255) / 256, 256>>>(bat, gptr);

    // 3) layer 0 (input width 9) — FFMA path for K=9
    k_aggregate<<<NN, 32>>>(x, agg, rowptr, col, INF);
    sgemm(NN, HID, INF, agg, w1_0, b1_0, t1, 1);
    gemm_f16(NN, HID, HID, t1, w2_0, b2_0, h, 1);  // fused inter-layer relu

    // 4) layers 1..4 — tensor-core GEMMs
    for (int i = 0; i < 4; i++) {
        k_aggregate_v4<<<NN, 160>>>(h, agg, rowptr, col);
        gemm_f16(NN, HID, HID, agg, w1_r + i * HID * HID, b1_r + i * HID, t1, 1);
        gemm_f16(NN, HID, HID, t1, w2_r + i * HID * HID, b2_r + i * HID, h, (i < 3) ? 1 : 0);
    }

    // 5) global_add_pool (segmented, batch_ind sorted)
    k_pool2<<<NG, 160>>>(h, gptr, feats);

    // 6) classifier MLP (small — FFMA path)
    sgemm(NG, CHID, HID, feats, cw1, cb1, z1, 1);
    sgemm(NG, CHID, CHID, z1, cw2, cb2, z2, 1);
    sgemm(NG, NT, CHID, z2, cw3, cb3, out, 0);
}

// round 14
// speedup vs baseline: 2.7342x; 1.0540x over previous
#include <cuda_runtime.h>
#include <cstdint>

// Problem constants (match reference)
#define NN   30000
#define EE   300000
#define NG   512
#define HID  600
#define INF  9
#define NT   128
#define CHID 256
#define KP2  (HID / 2)        // 300 pair-words per row
#define WSZ  (KP2 * HID)      // 180000 words per packed weight

// ---------------- device scratch (allocation-free rule: device globals) ----
__device__ float g_h[NN * HID];
__device__ float g_agg9[NN * INF];
__device__ float g_feats[NG * HID];
__device__ float g_z1[NG * CHID];
__device__ float g_z2[NG * CHID];
__device__ uint32_t g_aggh[NN * KP2];
__device__ uint32_t g_aggl[NN * KP2];
__device__ uint32_t g_t1h[NN * KP2];
__device__ uint32_t g_t1l[NN * KP2];
__device__ uint32_t g_wh[9 * WSZ];
__device__ uint32_t g_wl[9 * WSZ];

__device__ int g_src[EE];
__device__ int g_dst[EE];
__device__ int g_batch[NN];
__device__ int g_deg[NN];
__device__ int g_rowptr[NN + 1];
__device__ int g_cursor[NN];
__device__ int g_col[EE];
__device__ int g_gptr[NG + 1];
__device__ int g_is64;

// fp16 conversions via PTX (avoids cuda_fp16.h)
__device__ __forceinline__ void pack_pair(float v0, float v1,
                                          uint32_t& wh, uint32_t& wl) {
    unsigned short h0, h1, l0, l1;
    float b0, b1;
    asm("cvt.rn.f16.f32 %0, %1;" : "=h"(h0) : "f"(v0));
    asm("cvt.rn.f16.f32 %0, %1;" : "=h"(h1) : "f"(v1));
    asm("cvt.f32.f16 %0, %1;" : "=f"(b0) : "h"(h0));
    asm("cvt.f32.f16 %0, %1;" : "=f"(b1) : "h"(h1));
    float r0 = v0 - b0, r1 = v1 - b1;
    asm("cvt.rn.f16.f32 %0, %1;" : "=h"(l0) : "f"(r0));
    asm("cvt.rn.f16.f32 %0, %1;" : "=h"(l1) : "f"(r1));
    wh = (uint32_t)h0 | ((uint32_t)h1 << 16);
    wl = (uint32_t)l0 | ((uint32_t)l1 << 16);
}

// ---------------- index dtype detection + conversion ----------------------
__global__ void k_detect(const unsigned long long* __restrict__ p) {
    if (threadIdx.x == 0 && blockIdx.x == 0) {
        int is64 = 1;
        for (int i = 0; i < 256; i++)
            if (p[i] >> 32) { is64 = 0; break; }
        g_is64 = is64;
    }
}

__global__ void k_convert(const void* __restrict__ edges,
                          const void* __restrict__ batch) {
    int i = blockIdx.x * blockDim.x + threadIdx.x;
    int is64 = g_is64;
    if (i < EE) {
        if (is64) {
            const long long* p = (const long long*)edges;
            g_src[i] = (int)p[i];
            g_dst[i] = (int)p[EE + i];
        } else {
            const int* p = (const int*)edges;
            g_src[i] = p[i];
            g_dst[i] = p[EE + i];
        }
    }
    if (i < NN) {
        if (is64) {
            const long long* p = (const long long*)batch;
            g_batch[i] = (int)p[i];
        } else {
            const int* p = (const int*)batch;
            g_batch[i] = p[i];
        }
    }
}

// ---------------- weight pre-packing ---------------------------------------
__global__ void k_convw(const float* __restrict__ w, uint32_t* __restrict__ wh,
                        uint32_t* __restrict__ wl) {
    int idx = blockIdx.x * blockDim.x + threadIdx.x;   // 0..WSZ-1
    if (idx >= WSZ) return;
    int kp = idx / HID, n = idx - kp * HID;
    float v0 = w[(2 * kp) * HID + n];
    float v1 = w[(2 * kp + 1) * HID + n];
    uint32_t a, b;
    pack_pair(v0, v1, a, b);
    wh[idx] = a;
    wl[idx] = b;
}

// ---------------- small utility kernels ------------------------------------
__global__ void k_zero_int(int* p, int n) {
    int i = blockIdx.x * blockDim.x + threadIdx.x;
    if (i < n) p[i] = 0;
}
__global__ void k_copy_int(const int* __restrict__ a, int* __restrict__ b, int n) {
    int i = blockIdx.x * blockDim.x + threadIdx.x;
    if (i < n) b[i] = a[i];
}

// ---------------- CSR build (dst-major) ------------------------------------
__global__ void k_count(const int* __restrict__ dst, int* __restrict__ deg) {
    int i = blockIdx.x * blockDim.x + threadIdx.x;
    if (i < EE) atomicAdd(&deg[dst[i]], 1);
}

__global__ void k_scan(const int* __restrict__ in, int* __restrict__ out, int n) {
    __shared__ int s[1024];
    __shared__ int s_carry;
    int tid = threadIdx.x;
    if (tid == 0) s_carry = 0;
    __syncthreads();
    for (int base = 0; base < n; base += 1024) {
        int i = base + tid;
        int v = (i < n) ? in[i] : 0;
        s[tid] = v;
        __syncthreads();
        for (int off = 1; off < 1024; off <<= 1) {
            int t = (tid >= off) ? s[tid - off] : 0;
            __syncthreads();
            s[tid] += t;
            __syncthreads();
        }
        int c = s_carry;
        if (i < n) out[i] = c + s[tid] - v;
        __syncthreads();
        if (tid == 0) s_carry = c + s[1023];
        __syncthreads();
    }
    if (tid == 0) out[n] = s_carry;
}

__global__ void k_fill(const int* __restrict__ src, const int* __restrict__ dst,
                       int* __restrict__ cursor, int* __restrict__ col) {
    int i = blockIdx.x * blockDim.x + threadIdx.x;
    if (i < EE) {
        int p = atomicAdd(&cursor[dst[i]], 1);
        col[p] = src[i];
    }
}

// ---------------- graph ranges (batch_ind is sorted) -----------------------
__global__ void k_gptr(const int* __restrict__ batch, int* __restrict__ gptr) {
    int g = blockIdx.x * blockDim.x + threadIdx.x;
    if (g > NG) return;
    int lo = 0, hi = NN;
    while (lo < hi) {
        int mid = (lo + hi) >> 1;
        if (batch[mid] < g) lo = mid + 1; else hi = mid;
    }
    gptr[g] = lo;
}

// ---------------- aggregation ----------------------------------------------
// layer0 (width 9, fp32 out)
__global__ void k_aggregate(const float* __restrict__ h, float* __restrict__ agg,
                            const int* __restrict__ rowptr,
                            const int* __restrict__ col, int width) {
    __shared__ int s_nbr[64];
    int node = blockIdx.x;
    int f = threadIdx.x;
    int CH = (blockDim.x < 64) ? blockDim.x : 64;
    int start = rowptr[node], end = rowptr[node + 1];
    float acc = (f < width) ? h[node * width + f] : 0.f;
    for (int base = start; base < end; base += CH) {
        int cnt = end - base;
        if (cnt > CH) cnt = CH;
        if ((int)threadIdx.x < cnt) s_nbr[threadIdx.x] = col[base + threadIdx.x];
        __syncthreads();
        if (f < width) {
            for (int j = 0; j < cnt; j++)
                acc += h[s_nbr[j] * width + f];
        }
        __syncthreads();
    }
    if (f < width) agg[node * width + f] = acc;
}

// width-600, packed hi/lo pair output
__global__ void k_aggregate_pk(const float* __restrict__ h,
                               uint32_t* __restrict__ aggh,
                               uint32_t* __restrict__ aggl,
                               const int* __restrict__ rowptr,
                               const int* __restrict__ col) {
    __shared__ int s_nbr[32];
    int node = blockIdx.x;
    int f4 = threadIdx.x;                  // 0..159, use first 150
    int start = rowptr[node], end = rowptr[node + 1];
    const float4* hv = (const float4*)h;
    float4 acc;
    if (f4 < 150) acc = hv[node * 150 + f4];
    else acc = make_float4(0.f, 0.f, 0.f, 0.f);
    for (int base = start; base < end; base += 32) {
        int cnt = end - base;
        if (cnt > 32) cnt = 32;
        if ((int)threadIdx.x < cnt) s_nbr[threadIdx.x] = col[base + threadIdx.x];
        __syncthreads();
        if (f4 < 150) {
            for (int j = 0; j < cnt; j++) {
                float4 v = hv[s_nbr[j] * 150 + f4];
                acc.x += v.x; acc.y += v.y; acc.z += v.z; acc.w += v.w;
            }
        }
        __syncthreads();
    }
    if (f4 < 150) {
        uint32_t h0, l0, h1, l1;
        pack_pair(acc.x, acc.y, h0, l0);
        pack_pair(acc.z, acc.w, h1, l1);
        int off = node * KP2 + 2 * f4;
        *(uint2*)&aggh[off] = make_uint2(h0, h1);
        *(uint2*)&aggl[off] = make_uint2(l0, l1);
    }
}

// ---------------- pooling (segmented, no atomics) --------------------------
__global__ void k_pool2(const float* __restrict__ h, const int* __restrict__ gptr,
                        float* __restrict__ feats) {
    int g = blockIdx.x;
    int f4 = threadIdx.x;
    if (f4 >= 150) return;
    int start = gptr[g], end = gptr[g + 1];
    const float4* hv = (const float4*)h;
    float4 acc = make_float4(0.f, 0.f, 0.f, 0.f);
    for (int n = start; n < end; n++) {
        float4 v = hv[n * 150 + f4];
        acc.x += v.x; acc.y += v.y; acc.z += v.z; acc.w += v.w;
    }
    ((float4*)feats)[g * 150 + f4] = acc;
}

// ---------------- FFMA SGEMM (layer0 K=9, classifier; optional packed out) --
#define BM 128
#define BN 128
#define BK 8

__global__ __launch_bounds__(256)
void k_sgemm(int M, int N, int K,
             const float* __restrict__ A, const float* __restrict__ B,
             const float* __restrict__ bias, float* __restrict__ C,
             uint32_t* __restrict__ Ch, uint32_t* __restrict__ Cl,
             int relu, int packout) {
    __shared__ float As[BK][BM + 4];
    __shared__ float Bs[BK][BN];

    int tid = threadIdx.x;
    int tx = tid & 15;
    int ty = tid >> 4;
    int m0 = blockIdx.y * BM;
    int n0 = blockIdx.x * BN;

    float acc[8][8];
#pragma unroll
    for (int i = 0; i < 8; i++)
#pragma unroll
        for (int j = 0; j < 8; j++) acc[i][j] = 0.f;

    for (int k0 = 0; k0 < K; k0 += BK) {
#pragma unroll
        for (int i = 0; i < 4; i++) {
            int e = tid * 4 + i;
            int m = e >> 3, k = e & 7;
            int gm = m0 + m, gk = k0 + k;
            As[k][m] = (gm < M && gk < K) ? A[gm * K + gk] : 0.f;
        }
#pragma unroll
        for (int i = 0; i < 4; i++) {
            int e = tid * 4 + i;
            int k = e >> 7, n = e & 127;
            int gn = n0 + n, gk = k0 + k;
            Bs[k][n] = (gn < N && gk < K) ? B[gk * N + gn] : 0.f;
        }
        __syncthreads();

#pragma unroll
        for (int k = 0; k < BK; k++) {
            float4 a0 = *(const float4*)&As[k][ty * 4];
            float4 a1 = *(const float4*)&As[k][64 + ty * 4];
            float4 b0 = *(const float4*)&Bs[k][tx * 4];
            float4 b1 = *(const float4*)&Bs[k][64 + tx * 4];
            float a[8] = {a0.x, a0.y, a0.z, a0.w, a1.x, a1.y, a1.z, a1.w};
            float b[8] = {b0.x, b0.y, b0.z, b0.w, b1.x, b1.y, b1.z, b1.w};
#pragma unroll
            for (int i = 0; i < 8; i++)
#pragma unroll
                for (int j = 0; j < 8; j++)
                    acc[i][j] = fmaf(a[i], b[j], acc[i][j]);
        }
        __syncthreads();
    }

#pragma unroll
    for (int i = 0; i < 8; i++) {
        int r = (i < 4) ? (ty * 4 + i) : (64 + ty * 4 + (i - 4));
        int gm = m0 + r;
        if (gm >= M) continue;
        if (packout) {
#pragma unroll
            for (int j = 0; j < 8; j += 2) {
                int c = (j < 4) ? (tx * 4 + j) : (64 + tx * 4 + (j - 4));
                int gn = n0 + c;
                if (gn >= N) continue;
                float v0 = acc[i][j] + bias[gn];
                float v1 = acc[i][j + 1] + bias[gn + 1];
                if (relu) { v0 = fmaxf(v0, 0.f); v1 = fmaxf(v1, 0.f); }
                uint32_t wh, wl;
                pack_pair(v0, v1, wh, wl);
                int p = gm * (N >> 1) + (gn >> 1);
                Ch[p] = wh;
                Cl[p] = wl;
            }
        } else {
#pragma unroll
            for (int j = 0; j < 8; j++) {
                int c = (j < 4) ? (tx * 4 + j) : (64 + tx * 4 + (j - 4));
                int gn = n0 + c;
                if (gn >= N) continue;
                float v = acc[i][j] + bias[gn];
                if (relu) v = fmaxf(v, 0.f);
                C[gm * N + gn] = v;
            }
        }
    }
}

// ---------------- 3xFP16 mma.sync GEMM, pre-packed operands ----------------
// D = act(A @ B + bias). A, B given as pair-packed hi/lo arrays
// (word kp = half2(v[2kp], v[2kp+1])). Loader is pure LDG->STS, zero cvt.
// Output: fp32 C, or pair-packed Ch/Cl (for the next GEMM's A).
#define GBM 128
#define GBN 128
#define GBK 16
#define PST 136
#define REGW (8 * PST)
#define BUFW (4 * REGW)
#define OA_HI 0
#define OA_LO REGW
#define OB_HI (2 * REGW)
#define OB_LO (3 * REGW)

__device__ __forceinline__ void mma_f16(float* d, const uint32_t* a,
                                        uint32_t b0, uint32_t b1) {
    asm volatile(
        "mma.sync.aligned.m16n8k16.row.col.f32.f16.f16.f32 "
        "{%0,%1,%2,%3}, {%4,%5,%6,%7}, {%8,%9}, {%0,%1,%2,%3};\n"
        : "+f"(d[0]), "+f"(d[1]), "+f"(d[2]), "+f"(d[3])
        : "r"(a[0]), "r"(a[1]), "r"(a[2]), "r"(a[3]), "r"(b0), "r"(b1));
}

__global__ __launch_bounds__(256, 2)
void k_gemm_f16(int M, int N, int K,
                const uint32_t* __restrict__ Ah, const uint32_t* __restrict__ Al,
                const uint32_t* __restrict__ Bh, const uint32_t* __restrict__ Bl,
                const float* __restrict__ bias,
                float* __restrict__ C,
                uint32_t* __restrict__ Ch, uint32_t* __restrict__ Cl,
                int relu, int packout) {
    __shared__ uint32_t sh[2][BUFW];

    int KPa = K >> 1;                 // pair rows
    int tid = threadIdx.x;
    int lane = tid & 31;
    int warp = tid >> 5;
    int wm = (warp >> 1) * 32;
    int wn = (warp & 1) * 64;
    int lq = lane >> 2;
    int lr = lane & 3;

    int m0 = blockIdx.y * GBM;
    int n0 = blockIdx.x * GBN;

    // A loader: row am, 4 pair-words starting at tile pair-row akp
    int am = tid >> 1;
    int akp = (tid & 1) * 4;
    int gmA = m0 + am;
    bool a_ok = (gmA < M);
    // B loader: pair-row kb (0..7), 4 n-words at nb
    int kb = tid >> 5;
    int nb = (tid & 31) * 4;

    float acc[2][8][4];
#pragma unroll
    for (int i = 0; i < 2; i++)
#pragma unroll
        for (int j = 0; j < 8; j++)
#pragma unroll
            for (int c = 0; c < 4; c++) acc[i][j][c] = 0.f;

    uint32_t rah[4], ral[4], rbh[4], rbl[4];
    int NIT = (K + GBK - 1) / GBK;

    // ---- prologue: load tile 0 ----
    {
        int pk0 = akp;
        if (a_ok && pk0 + 4 <= KPa) {
            uint4 vh = *(const uint4*)&Ah[gmA * KPa + pk0];
            uint4 vl = *(const uint4*)&Al[gmA * KPa + pk0];
            rah[0] = vh.x; rah[1] = vh.y; rah[2] = vh.z; rah[3] = vh.w;
            ral[0] = vl.x; ral[1] = vl.y; ral[2] = vl.z; ral[3] = vl.w;
        } else {
#pragma unroll
            for (int i = 0; i < 4; i++) {
                bool ok = a_ok && (pk0 + i < KPa);
                rah[i] = ok ? Ah[gmA * KPa + pk0 + i] : 0u;
                ral[i] = ok ? Al[gmA * KPa + pk0 + i] : 0u;
            }
        }
        int kpg = kb;
        int gn = n0 + nb;
        if (kpg < KPa && gn + 4 <= N) {
            uint4 vh = *(const uint4*)&Bh[kpg * N + gn];
            uint4 vl = *(const uint4*)&Bl[kpg * N + gn];
            rbh[0] = vh.x; rbh[1] = vh.y; rbh[2] = vh.z; rbh[3] = vh.w;
            rbl[0] = vl.x; rbl[1] = vl.y; rbl[2] = vl.z; rbl[3] = vl.w;
        } else {
#pragma unroll
            for (int j = 0; j < 4; j++) {
                bool ok = (kpg < KPa) && (gn + j < N);
                rbh[j] = ok ? Bh[kpg * N + gn + j] : 0u;
                rbl[j] = ok ? Bl[kpg * N + gn + j] : 0u;
            }
        }
        uint32_t* buf = sh[0];
#pragma unroll
        for (int i = 0; i < 4; i++) {
            buf[OA_HI + (akp + i) * PST + am] = rah[i];
            buf[OA_LO + (akp + i) * PST + am] = ral[i];
        }
        *(uint4*)&buf[OB_HI + kb * PST + nb] = make_uint4(rbh[0], rbh[1], rbh[2], rbh[3]);
        *(uint4*)&buf[OB_LO + kb * PST + nb] = make_uint4(rbl[0], rbl[1], rbl[2], rbl[3]);
    }
    __syncthreads();

    int buf_i = 0;
    for (int it = 0; it < NIT; it++) {
        bool has_next = (it + 1 < NIT);
        // ---- prefetch next tile ----
        if (has_next) {
            int pk0 = ((it + 1) * GBK >> 1) + akp;
            if (a_ok && pk0 + 4 <= KPa) {
                uint4 vh = *(const uint4*)&Ah[gmA * KPa + pk0];
                uint4 vl = *(const uint4*)&Al[gmA * KPa + pk0];
                rah[0] = vh.x; rah[1] = vh.y; rah[2] = vh.z; rah[3] = vh.w;
                ral[0] = vl.x; ral[1] = vl.y; ral[2] = vl.z; ral[3] = vl.w;
            } else {
#pragma unroll
                for (int i = 0; i < 4; i++) {
                    bool ok = a_ok && (pk0 + i < KPa);
                    rah[i] = ok ? Ah[gmA * KPa + pk0 + i] : 0u;
                    ral[i] = ok ? Al[gmA * KPa + pk0 + i] : 0u;
                }
            }
            int kpg = ((it + 1) * GBK >> 1) + kb;
            int gn = n0 + nb;
            if (kpg < KPa && gn + 4 <= N) {
                uint4 vh = *(const uint4*)&Bh[kpg * N + gn];
                uint4 vl = *(const uint4*)&Bl[kpg * N + gn];
                rbh[0] = vh.x; rbh[1] = vh.y; rbh[2] = vh.z; rbh[3] = vh.w;
                rbl[0] = vl.x; rbl[1] = vl.y; rbl[2] = vl.z; rbl[3] = vl.w;
            } else {
#pragma unroll
                for (int j = 0; j < 4; j++) {
                    bool ok = (kpg < KPa) && (gn + j < N);
                    rbh[j] = ok ? Bh[kpg * N + gn + j] : 0u;
                    rbl[j] = ok ? Bl[kpg * N + gn + j] : 0u;
                }
            }
        }

        // ---- compute on current buffer ----
        const uint32_t* bufc = sh[buf_i];
        uint32_t ah[2][4], al[2][4];
#pragma unroll
        for (int i = 0; i < 2; i++) {
            int r1 = wm + i * 16 + lq;
            ah[i][0] = bufc[OA_HI + lr * PST + r1];
            ah[i][1] = bufc[OA_HI + lr * PST + r1 + 8];
            ah[i][2] = bufc[OA_HI + (lr + 4) * PST + r1];
            ah[i][3] = bufc[OA_HI + (lr + 4) * PST + r1 + 8];
            al[i][0] = bufc[OA_LO + lr * PST + r1];
            al[i][1] = bufc[OA_LO + lr * PST + r1 + 8];
            al[i][2] = bufc[OA_LO + (lr + 4) * PST + r1];
            al[i][3] = bufc[OA_LO + (lr + 4) * PST + r1 + 8];
        }
#pragma unroll
        for (int j = 0; j < 8; j++) {
            int n = wn + j * 8 + lq;
            uint32_t bh0 = bufc[OB_HI + lr * PST + n];
            uint32_t bh1 = bufc[OB_HI + (lr + 4) * PST + n];
            uint32_t bl0 = bufc[OB_LO + lr * PST + n];
            uint32_t bl1 = bufc[OB_LO + (lr + 4) * PST + n];
            mma_f16(acc[0][j], ah[0], bh0, bh1);
            mma_f16(acc[1][j], ah[1], bh0, bh1);
            mma_f16(acc[0][j], ah[0], bl0, bl1);
            mma_f16(acc[1][j], ah[1], bl0, bl1);
            mma_f16(acc[0][j], al[0], bh0, bh1);
            mma_f16(acc[1][j], al[1], bh0, bh1);
        }

        // ---- STS next tile ----
        if (has_next) {
            uint32_t* bufn = sh[buf_i ^ 1];
#pragma unroll
            for (int i = 0; i < 4; i++) {
                bufn[OA_HI + (akp + i) * PST + am] = rah[i];
                bufn[OA_LO + (akp + i) * PST + am] = ral[i];
            }
            *(uint4*)&bufn[OB_HI + kb * PST + nb] = make_uint4(rbh[0], rbh[1], rbh[2], rbh[3]);
            *(uint4*)&bufn[OB_LO + kb * PST + nb] = make_uint4(rbl[0], rbl[1], rbl[2], rbl[3]);
        }
        __syncthreads();
        buf_i ^= 1;
    }

    // ---- epilogue ----
    int lr2 = 2 * lr;
    if (packout) {
        int NP = N >> 1;
#pragma unroll
        for (int i = 0; i < 2; i++) {
            int colp = n0 + wn + lr2;
#pragma unroll
            for (int j = 0; j < 8; j++) {
                int col = colp + j * 8;
                if (col >= N) continue;
                int pidx = col >> 1;
                float bi0 = bias[col], bi1 = bias[col + 1];
                int r0 = m0 + wm + i * 16 + lq;
                if (r0 < M) {
                    float v0 = acc[i][j][0] + bi0;
                    float v1 = acc[i][j][1] + bi1;
                    if (relu) { v0 = fmaxf(v0, 0.f); v1 = fmaxf(v1, 0.f); }
                    uint32_t wh, wl;
                    pack_pair(v0, v1, wh, wl);
                    Ch[r0 * NP + pidx] = wh;
                    Cl[r0 * NP + pidx] = wl;
                }
                int r1 = r0 + 8;
                if (r1 < M) {
                    float v0 = acc[i][j][2] + bi0;
                    float v1 = acc[i][j][3] + bi1;
                    if (relu) { v0 = fmaxf(v0, 0.f); v1 = fmaxf(v1, 0.f); }
                    uint32_t wh, wl;
                    pack_pair(v0, v1, wh, wl);
                    Ch[r1 * NP + pidx] = wh;
                    Cl[r1 * NP + pidx] = wl;
                }
            }
        }
    } else {
#pragma unroll
        for (int i = 0; i < 2; i++) {
#pragma unroll
            for (int c = 0; c < 4; c++) {
                int row = m0 + wm + i * 16 + lq + ((c >= 2) ? 8 : 0);
                if (row >= M) continue;
#pragma unroll
                for (int j = 0; j < 8; j++) {
                    int col = n0 + wn + j * 8 + lr2 + (c & 1);
                    if (col >= N) continue;
                    float v = acc[i][j][c] + bias[col];
                    if (relu) v = fmaxf(v, 0.f);
                    C[row * N + col] = v;
                }
            }
        }
    }
}

// ---------------- host orchestration ---------------------------------------
static inline void sgemm(int M, int N, int K, const float* A, const float* B,
                         const float* bias, float* C, uint32_t* Ch, uint32_t* Cl,
                         int relu, int packout) {
    dim3 grid((N + BN - 1) / BN, (M + BM - 1) / BM);
    k_sgemm<<<grid, 256>>>(M, N, K, A, B, bias, C, Ch, Cl, relu, packout);
}

static inline void gemm_f16(int M, int N, int K,
                            const uint32_t* Ah, const uint32_t* Al,
                            const uint32_t* Bh, const uint32_t* Bl,
                            const float* bias, float* C,
                            uint32_t* Ch, uint32_t* Cl, int relu, int packout) {
    dim3 grid((N + GBN - 1) / GBN, (M + GBM - 1) / GBM);
    k_gemm_f16<<<grid, 256>>>(M, N, K, Ah, Al, Bh, Bl, bias, C, Ch, Cl, relu, packout);
}

extern "C" void kernel_launch(void* const* d_in, const int* in_sizes, int n_in,
                              void* d_out, int out_size) {
    const float* x      = (const float*)d_in[0];
    const void*  edges  = d_in[1];
    const void*  batch  = d_in[2];
    const float* w1_0 = (const float*)d_in[3];
    const float* b1_0 = (const float*)d_in[4];
    const float* w2_0 = (const float*)d_in[5];
    const float* b2_0 = (const float*)d_in[6];
    const float* w1_r = (const float*)d_in[7];
    const float* b1_r = (const float*)d_in[8];
    const float* w2_r = (const float*)d_in[9];
    const float* b2_r = (const float*)d_in[10];
    const float* cw1  = (const float*)d_in[11];
    const float* cb1  = (const float*)d_in[12];
    const float* cw2  = (const float*)d_in[13];
    const float* cb2  = (const float*)d_in[14];
    const float* cw3  = (const float*)d_in[15];
    const float* cb3  = (const float*)d_in[16];
    float* out = (float*)d_out;

    float *h, *agg9, *feats, *z1, *z2;
    uint32_t *aggh, *aggl, *t1h, *t1l, *wh, *wl;
    int *src, *dst, *bat, *deg, *rowptr, *cursor, *col, *gptr;
    cudaGetSymbolAddress((void**)&h, g_h);
    cudaGetSymbolAddress((void**)&agg9, g_agg9);
    cudaGetSymbolAddress((void**)&feats, g_feats);
    cudaGetSymbolAddress((void**)&z1, g_z1);
    cudaGetSymbolAddress((void**)&z2, g_z2);
    cudaGetSymbolAddress((void**)&aggh, g_aggh);
    cudaGetSymbolAddress((void**)&aggl, g_aggl);
    cudaGetSymbolAddress((void**)&t1h, g_t1h);
    cudaGetSymbolAddress((void**)&t1l, g_t1l);
    cudaGetSymbolAddress((void**)&wh, g_wh);
    cudaGetSymbolAddress((void**)&wl, g_wl);
    cudaGetSymbolAddress((void**)&src, g_src);
    cudaGetSymbolAddress((void**)&dst, g_dst);
    cudaGetSymbolAddress((void**)&bat, g_batch);
    cudaGetSymbolAddress((void**)&deg, g_deg);
    cudaGetSymbolAddress((void**)&rowptr, g_rowptr);
    cudaGetSymbolAddress((void**)&cursor, g_cursor);
    cudaGetSymbolAddress((void**)&col, g_col);
    cudaGetSymbolAddress((void**)&gptr, g_gptr);

    // 1) index dtype detect + convert
    k_detect<<<1, 32>>>((const unsigned long long*)edges);
    {
        int n = (EE > NN) ? EE : NN;
        k_convert<<<(n + 255) / 256, 256>>>(edges, batch);
    }

    // 2) CSR build + graph ranges + weight packing
    k_zero_int<<<(NN + 255) / 256, 256>>>(deg, NN);
    k_count<<<(EE + 255) / 256, 256>>>(dst, deg);
    k_scan<<<1, 1024>>>(deg, rowptr, NN);
    k_copy_int<<<(NN + 255) / 256, 256>>>(rowptr, cursor, NN);
    k_fill<<<(EE + 255) / 256, 256>>>(src, dst, cursor, col);
    k_gptr<<<(NG + 1 + 255) / 256, 256>>>(bat, gptr);
    {
        int wgrid = (WSZ + 255) / 256;
        k_convw<<<wgrid, 256>>>(w2_0, wh, wl);
        for (int i = 0; i < 4; i++) {
            k_convw<<<wgrid, 256>>>(w1_r + i * HID * HID,
                                    wh + (1 + 2 * i) * WSZ, wl + (1 + 2 * i) * WSZ);
            k_convw<<<wgrid, 256>>>(w2_r + i * HID * HID,
                                    wh + (2 + 2 * i) * WSZ, wl + (2 + 2 * i) * WSZ);
        }
    }

    // 3) layer 0
    k_aggregate<<<NN, 32>>>(x, agg9, rowptr, col, INF);
    sgemm(NN, HID, INF, agg9, w1_0, b1_0, nullptr, t1h, t1l, 1, 1);
    gemm_f16(NN, HID, HID, t1h, t1l, wh, wl, b2_0, h, nullptr, nullptr, 1, 0);

    // 4) layers 1..4
    for (int i = 0; i < 4; i++) {
        k_aggregate_pk<<<NN, 160>>>(h, aggh, aggl, rowptr, col);
        gemm_f16(NN, HID, HID, aggh, aggl,
                 wh + (1 + 2 * i) * WSZ, wl + (1 + 2 * i) * WSZ,
                 b1_r + i * HID, nullptr, t1h, t1l, 1, 1);
        gemm_f16(NN, HID, HID, t1h, t1l,
                 wh + (2 + 2 * i) * WSZ, wl + (2 + 2 * i) * WSZ,
                 b2_r + i * HID, h, nullptr, nullptr, (i < 3) ? 1 : 0, 0);
    }

    // 5) global_add_pool
    k_pool2<<<NG, 160>>>(h, gptr, feats);

    // 6) classifier MLP
    sgemm(NG, CHID, HID, feats, cw1, cb1, z1, nullptr, nullptr, 1, 0);
    sgemm(NG, CHID, CHID, z1, cw2, cb2, z2, nullptr, nullptr, 1, 0);
    sgemm(NG, NT, CHID, z2, cw3, cb3, out, nullptr, nullptr, 0, 0);
}